// round 1
// baseline (speedup 1.0000x reference)
#include <cuda_runtime.h>
#include <cuda_bf16.h>

// ---------------- problem constants ----------------
#define NE    1200000   // raw edges
#define NN    100000    // nodes
#define TOTE  1300000   // edges + self loops
#define NI    40000
#define NU    30000
#define NF    30000

// d_out layout (float32), in reference return order
#define ITEMO  0
#define USERO  2560000
#define FETO   4480000
#define FINALO 6400000
#define A1OFF  12800000
#define A2OFF  15400000
#define A3OFF  18000000

// ---------------- device scratch (no allocations allowed) ----------------
__device__ float g_x0[NN * 64];
__device__ float g_xw[NN * 128];
__device__ float g_h[NN * 128];
__device__ float g_facc[NN * 64];
__device__ float g_asrc[NN * 2];
__device__ float g_adst[NN * 2];
__device__ int   g_count[NN];
__device__ int   g_offs[NN + 1];
__device__ int   g_cursor[NN];
__device__ int   g_perm[TOTE];

// ---------------- CSR build ----------------
__global__ void zero_count_kernel() {
    int i = blockIdx.x * blockDim.x + threadIdx.x;
    if (i < NN) g_count[i] = 0;
}

__global__ void hist_kernel(const int* __restrict__ ei) {
    int e = blockIdx.x * blockDim.x + threadIdx.x;
    if (e >= TOTE) return;
    int d = (e < NE) ? ei[NE + e] : (e - NE);
    atomicAdd(&g_count[d], 1);
}

__global__ void scan_kernel() {
    __shared__ int part[1024];
    int t = threadIdx.x;
    const int CH = 98;  // 1024*98 >= NN
    int base = t * CH;
    int s = 0;
    for (int i = 0; i < CH; i++) {
        int idx = base + i;
        if (idx < NN) s += g_count[idx];
    }
    part[t] = s;
    __syncthreads();
    for (int off = 1; off < 1024; off <<= 1) {
        int v = (t >= off) ? part[t - off] : 0;
        __syncthreads();
        part[t] += v;
        __syncthreads();
    }
    int ex = (t == 0) ? 0 : part[t - 1];
    for (int i = 0; i < CH; i++) {
        int idx = base + i;
        if (idx < NN) {
            g_offs[idx] = ex;
            g_cursor[idx] = ex;
            ex += g_count[idx];
        }
    }
    if (t == 0) g_offs[NN] = part[1023];
}

__global__ void scatter_kernel(const int* __restrict__ ei) {
    int e = blockIdx.x * blockDim.x + threadIdx.x;
    if (e >= TOTE) return;
    int d = (e < NE) ? ei[NE + e] : (e - NE);
    int pos = atomicAdd(&g_cursor[d], 1);
    g_perm[pos] = e;
}

// ---------------- x0 = concat(item,user,fet) ----------------
__global__ void build_x0_kernel(const float* __restrict__ a,
                                const float* __restrict__ b,
                                const float* __restrict__ c) {
    int i = blockIdx.x * blockDim.x + threadIdx.x;  // over NN*16 float4
    if (i >= NN * 16) return;
    int v = i >> 4;
    float4 val;
    if (v < NI)            val = ((const float4*)a)[i];
    else if (v < NI + NU)  val = ((const float4*)b)[i - NI * 16];
    else                   val = ((const float4*)c)[i - (NI + NU) * 16];
    ((float4*)g_x0)[i] = val;
}

// ---------------- SGEMM: C[M,NC] = A[M,K] @ B[K,NC] ----------------
// BM=64, BN=64, BK=16, 256 threads, 4x4 per thread
template <int K, int NC>
__global__ void sgemm_kernel(const float* __restrict__ A,
                             const float* __restrict__ B,
                             float* __restrict__ C, int M) {
    __shared__ float As[16][64];
    __shared__ float Bs[16][64];
    int tid = threadIdx.x;
    int tr = tid / 16, tc = tid % 16;
    int rowBase = blockIdx.x * 64;
    int colBase = blockIdx.y * 64;
    float acc[4][4] = {};
    for (int k0 = 0; k0 < K; k0 += 16) {
        #pragma unroll
        for (int i = 0; i < 4; i++) {
            int idx = tid + i * 256;
            int r = idx >> 4, c = idx & 15;
            float v = 0.f;
            if (rowBase + r < M) v = A[(long)(rowBase + r) * K + k0 + c];
            As[c][r] = v;
        }
        #pragma unroll
        for (int i = 0; i < 4; i++) {
            int idx = tid + i * 256;
            int r = idx >> 6, c = idx & 63;
            Bs[r][c] = B[(k0 + r) * NC + colBase + c];
        }
        __syncthreads();
        #pragma unroll
        for (int kk = 0; kk < 16; kk++) {
            float a[4], b[4];
            #pragma unroll
            for (int i = 0; i < 4; i++) a[i] = As[kk][tr * 4 + i];
            #pragma unroll
            for (int j = 0; j < 4; j++) b[j] = Bs[kk][tc * 4 + j];
            #pragma unroll
            for (int i = 0; i < 4; i++)
                #pragma unroll
                for (int j = 0; j < 4; j++)
                    acc[i][j] += a[i] * b[j];
        }
        __syncthreads();
    }
    #pragma unroll
    for (int i = 0; i < 4; i++) {
        int row = rowBase + tr * 4 + i;
        if (row >= M) continue;
        #pragma unroll
        for (int j = 0; j < 4; j++)
            C[(long)row * NC + colBase + tc * 4 + j] = acc[i][j];
    }
}

// ---------------- attention dots: a_src/a_dst per node per head ----------------
template <int HEADS>
__global__ void att_kernel(const float* __restrict__ xw,
                           const float* __restrict__ vs,
                           const float* __restrict__ vd) {
    int w = (blockIdx.x * blockDim.x + threadIdx.x) >> 5;
    if (w >= NN) return;
    int lane = threadIdx.x & 31;
    const int NC = HEADS * 64;
    #pragma unroll
    for (int h = 0; h < HEADS; h++) {
        float xa = xw[(long)w * NC + h * 64 + lane];
        float xb = xw[(long)w * NC + h * 64 + 32 + lane];
        float s = xa * vs[h * 64 + lane] + xb * vs[h * 64 + 32 + lane];
        float d = xa * vd[h * 64 + lane] + xb * vd[h * 64 + 32 + lane];
        #pragma unroll
        for (int o = 16; o; o >>= 1) {
            s += __shfl_xor_sync(0xffffffffu, s, o);
            d += __shfl_xor_sync(0xffffffffu, d, o);
        }
        if (lane == 0) {
            g_asrc[w * HEADS + h] = s;
            g_adst[w * HEADS + h] = d;
        }
    }
}

__device__ __forceinline__ float lrelu(float x) { return x > 0.f ? x : 0.2f * x; }

// ---------------- aggregation, H=2, C=64, concat; warp per dst node ----------------
// mode 1: facc = x0 + 0.5*(head0+head1);  mode 2: facc += 0.5*(head0+head1)
__global__ void agg_h2_kernel(const float* __restrict__ xw,
                              const int* __restrict__ ei,
                              const float* __restrict__ bias,
                              float* __restrict__ hout,
                              float* __restrict__ alpha_out,
                              int mode) {
    int v = (blockIdx.x * blockDim.x + threadIdx.x) >> 5;
    if (v >= NN) return;
    int lane = threadIdx.x & 31;
    int beg = g_offs[v];
    int deg = g_offs[v + 1] - beg;
    float ad0 = g_adst[2 * v], ad1 = g_adst[2 * v + 1];

    // pass 1: segment max per head
    float m0 = -3.0e38f, m1 = -3.0e38f;
    for (int i = lane; i < deg; i += 32) {
        int eid = g_perm[beg + i];
        int s = (eid < NE) ? ei[eid] : (eid - NE);
        float e0 = lrelu(g_asrc[2 * s] + ad0);
        float e1 = lrelu(g_asrc[2 * s + 1] + ad1);
        m0 = fmaxf(m0, e0);
        m1 = fmaxf(m1, e1);
    }
    #pragma unroll
    for (int o = 16; o; o >>= 1) {
        m0 = fmaxf(m0, __shfl_xor_sync(0xffffffffu, m0, o));
        m1 = fmaxf(m1, __shfl_xor_sync(0xffffffffu, m1, o));
    }

    // pass 2: denom per head
    float s0 = 0.f, s1 = 0.f;
    for (int i = lane; i < deg; i += 32) {
        int eid = g_perm[beg + i];
        int s = (eid < NE) ? ei[eid] : (eid - NE);
        float e0 = lrelu(g_asrc[2 * s] + ad0);
        float e1 = lrelu(g_asrc[2 * s + 1] + ad1);
        s0 += __expf(e0 - m0);
        s1 += __expf(e1 - m1);
    }
    #pragma unroll
    for (int o = 16; o; o >>= 1) {
        s0 += __shfl_xor_sync(0xffffffffu, s0, o);
        s1 += __shfl_xor_sync(0xffffffffu, s1, o);
    }
    float inv0 = 1.f / (s0 + 1e-16f);
    float inv1 = 1.f / (s1 + 1e-16f);

    // pass 3: alpha + weighted feature accumulation (lane owns 4 features)
    float4 acc = make_float4(0.f, 0.f, 0.f, 0.f);
    const float4* xw4 = (const float4*)xw;
    for (int base = 0; base < deg; base += 32) {
        int i = base + lane;
        float al0 = 0.f, al1 = 0.f;
        int s = 0;
        if (i < deg) {
            int eid = g_perm[beg + i];
            s = (eid < NE) ? ei[eid] : (eid - NE);
            float e0 = lrelu(g_asrc[2 * s] + ad0);
            float e1 = lrelu(g_asrc[2 * s + 1] + ad1);
            al0 = __expf(e0 - m0) * inv0;
            al1 = __expf(e1 - m1) * inv1;
            alpha_out[2 * eid] = al0;
            alpha_out[2 * eid + 1] = al1;
        }
        int cnt = min(32, deg - base);
        for (int t = 0; t < cnt; t++) {
            float a0 = __shfl_sync(0xffffffffu, al0, t);
            float a1 = __shfl_sync(0xffffffffu, al1, t);
            int st = __shfl_sync(0xffffffffu, s, t);
            float4 xv = xw4[(long)st * 32 + lane];
            float a = (lane < 16) ? a0 : a1;
            acc.x += a * xv.x;
            acc.y += a * xv.y;
            acc.z += a * xv.z;
            acc.w += a * xv.w;
        }
    }

    // epilogue: x = acc + bias; hout = relu(x); facc update
    int f = lane * 4;
    float xa = acc.x + bias[f];
    float xb = acc.y + bias[f + 1];
    float xc = acc.z + bias[f + 2];
    float xd = acc.w + bias[f + 3];
    float4 hv = make_float4(fmaxf(xa, 0.f), fmaxf(xb, 0.f), fmaxf(xc, 0.f), fmaxf(xd, 0.f));
    ((float4*)hout)[(long)v * 32 + lane] = hv;

    float pa = __shfl_xor_sync(0xffffffffu, xa, 16);
    float pb = __shfl_xor_sync(0xffffffffu, xb, 16);
    float pc = __shfl_xor_sync(0xffffffffu, xc, 16);
    float pd = __shfl_xor_sync(0xffffffffu, xd, 16);
    if (lane < 16) {
        float4 ev = make_float4(0.5f * (xa + pa), 0.5f * (xb + pb),
                                0.5f * (xc + pc), 0.5f * (xd + pd));
        long fidx = (long)v * 16 + lane;
        if (mode == 1) {
            float4 xv = ((const float4*)g_x0)[fidx];
            ev.x += xv.x; ev.y += xv.y; ev.z += xv.z; ev.w += xv.w;
        } else {
            float4 fv = ((const float4*)g_facc)[fidx];
            ev.x += fv.x; ev.y += fv.y; ev.z += fv.z; ev.w += fv.w;
        }
        ((float4*)g_facc)[fidx] = ev;
    }
}

// ---------------- aggregation, H=1, C=64 (layer 3) + final outputs ----------------
__global__ void agg_h1_kernel(const float* __restrict__ xw,
                              const int* __restrict__ ei,
                              const float* __restrict__ bias,
                              float* __restrict__ out) {
    int v = (blockIdx.x * blockDim.x + threadIdx.x) >> 5;
    if (v >= NN) return;
    int lane = threadIdx.x & 31;
    int beg = g_offs[v];
    int deg = g_offs[v + 1] - beg;
    float ad = g_adst[v];

    float m = -3.0e38f;
    for (int i = lane; i < deg; i += 32) {
        int eid = g_perm[beg + i];
        int s = (eid < NE) ? ei[eid] : (eid - NE);
        m = fmaxf(m, lrelu(g_asrc[s] + ad));
    }
    #pragma unroll
    for (int o = 16; o; o >>= 1) m = fmaxf(m, __shfl_xor_sync(0xffffffffu, m, o));

    float ssum = 0.f;
    for (int i = lane; i < deg; i += 32) {
        int eid = g_perm[beg + i];
        int s = (eid < NE) ? ei[eid] : (eid - NE);
        ssum += __expf(lrelu(g_asrc[s] + ad) - m);
    }
    #pragma unroll
    for (int o = 16; o; o >>= 1) ssum += __shfl_xor_sync(0xffffffffu, ssum, o);
    float inv = 1.f / (ssum + 1e-16f);

    float2 acc = make_float2(0.f, 0.f);
    const float2* xw2 = (const float2*)xw;
    for (int base = 0; base < deg; base += 32) {
        int i = base + lane;
        float al = 0.f;
        int s = 0;
        if (i < deg) {
            int eid = g_perm[beg + i];
            s = (eid < NE) ? ei[eid] : (eid - NE);
            al = __expf(lrelu(g_asrc[s] + ad) - m) * inv;
            out[A3OFF + eid] = al;
        }
        int cnt = min(32, deg - base);
        for (int t = 0; t < cnt; t++) {
            float a = __shfl_sync(0xffffffffu, al, t);
            int st = __shfl_sync(0xffffffffu, s, t);
            float2 xv = xw2[(long)st * 32 + lane];
            acc.x += a * xv.x;
            acc.y += a * xv.y;
        }
    }

    int f = lane * 2;
    float xa = acc.x + bias[f];
    float xb = acc.y + bias[f + 1];
    float fa = (g_facc[(long)v * 64 + f] + xa) * 0.25f;
    float fb = (g_facc[(long)v * 64 + f + 1] + xb) * 0.25f;
    out[FINALO + (long)v * 64 + f] = fa;
    out[FINALO + (long)v * 64 + f + 1] = fb;
    long seg;
    if (v < NI)            seg = ITEMO + (long)v * 64;
    else if (v < NI + NU)  seg = USERO + (long)(v - NI) * 64;
    else                   seg = FETO + (long)(v - NI - NU) * 64;
    out[seg + f] = fa;
    out[seg + f + 1] = fb;
}

// ---------------- host launch ----------------
extern "C" void kernel_launch(void* const* d_in, const int* in_sizes, int n_in,
                              void* d_out, int out_size) {
    const int*   ei       = (const int*)d_in[0];
    const float* emb_item = (const float*)d_in[1];
    const float* emb_user = (const float*)d_in[2];
    const float* emb_fet  = (const float*)d_in[3];
    const float* W1  = (const float*)d_in[4];
    const float* as1 = (const float*)d_in[5];
    const float* ad1 = (const float*)d_in[6];
    const float* b1  = (const float*)d_in[7];
    const float* W2  = (const float*)d_in[8];
    const float* as2 = (const float*)d_in[9];
    const float* ad2 = (const float*)d_in[10];
    const float* b2  = (const float*)d_in[11];
    const float* W3  = (const float*)d_in[12];
    const float* as3 = (const float*)d_in[13];
    const float* ad3 = (const float*)d_in[14];
    const float* b3  = (const float*)d_in[15];
    float* out = (float*)d_out;

    float *x0p, *xwp, *hp;
    cudaGetSymbolAddress((void**)&x0p, g_x0);
    cudaGetSymbolAddress((void**)&xwp, g_xw);
    cudaGetSymbolAddress((void**)&hp, g_h);

    const int T = 256;
    int nodeBlocks = (NN + T - 1) / T;
    int edgeBlocks = (TOTE + T - 1) / T;
    int warpBlocks = (NN * 32 + T - 1) / T;  // one warp per node

    // CSR build
    zero_count_kernel<<<nodeBlocks, T>>>();
    hist_kernel<<<edgeBlocks, T>>>(ei);
    scan_kernel<<<1, 1024>>>();
    scatter_kernel<<<edgeBlocks, T>>>(ei);

    // x0 concat
    build_x0_kernel<<<(NN * 16 + T - 1) / T, T>>>(emb_item, emb_user, emb_fet);

    // layer 1
    {
        dim3 g((NN + 63) / 64, 2);
        sgemm_kernel<64, 128><<<g, T>>>(x0p, W1, xwp, NN);
    }
    att_kernel<2><<<warpBlocks, T>>>(xwp, as1, ad1);
    agg_h2_kernel<<<warpBlocks, T>>>(xwp, ei, b1, hp, out + A1OFF, 1);

    // layer 2
    {
        dim3 g((NN + 63) / 64, 2);
        sgemm_kernel<128, 128><<<g, T>>>(hp, W2, xwp, NN);
    }
    att_kernel<2><<<warpBlocks, T>>>(xwp, as2, ad2);
    agg_h2_kernel<<<warpBlocks, T>>>(xwp, ei, b2, hp, out + A2OFF, 2);

    // layer 3
    {
        dim3 g((NN + 63) / 64, 1);
        sgemm_kernel<128, 64><<<g, T>>>(hp, W3, xwp, NN);
    }
    att_kernel<1><<<warpBlocks, T>>>(xwp, as3, ad3);
    agg_h1_kernel<<<warpBlocks, T>>>(xwp, ei, b3, out);
}

// round 2
// speedup vs baseline: 1.1575x; 1.1575x over previous
#include <cuda_runtime.h>
#include <cuda_bf16.h>

// ---------------- problem constants ----------------
#define NE    1200000   // raw edges
#define NN    100000    // nodes
#define TOTE  1300000   // edges + self loops
#define NI    40000
#define NU    30000
#define NF    30000

// d_out layout (float32), in reference return order
#define ITEMO  0
#define USERO  2560000
#define FETO   4480000
#define FINALO 6400000
#define A1OFF  12800000
#define A2OFF  15400000
#define A3OFF  18000000

// ---------------- device scratch (no allocations allowed) ----------------
__device__ float g_x0[NN * 64];
__device__ float g_xw[NN * 128];
__device__ float g_h[NN * 128];
__device__ float g_facc[NN * 64];
__device__ float g_asrc[NN * 2];
__device__ float g_adst[NN * 2];
__device__ int   g_count[NN];
__device__ int   g_offs[NN + 1];
__device__ int   g_cursor[NN];
__device__ int   g_perm[TOTE];

// ---------------- f32x2 packed helpers (SASS FFMA2 path) ----------------
__device__ __forceinline__ unsigned long long pk2(float x, float y) {
    unsigned long long r;
    asm("mov.b64 %0, {%1, %2};" : "=l"(r)
        : "r"(__float_as_uint(x)), "r"(__float_as_uint(y)));
    return r;
}
__device__ __forceinline__ void fma2(unsigned long long& d,
                                     unsigned long long a,
                                     unsigned long long b) {
    asm("fma.rn.f32x2 %0, %1, %2, %0;" : "+l"(d) : "l"(a), "l"(b));
}
__device__ __forceinline__ void unpk2(unsigned long long v, float& lo, float& hi) {
    unsigned a, b;
    asm("mov.b64 {%0, %1}, %2;" : "=r"(a), "=r"(b) : "l"(v));
    lo = __uint_as_float(a);
    hi = __uint_as_float(b);
}

// ---------------- CSR build ----------------
__global__ void zero_count_kernel() {
    int i = blockIdx.x * blockDim.x + threadIdx.x;
    if (i < NN) g_count[i] = 0;
}

__global__ void hist_kernel(const int* __restrict__ ei) {
    int e = blockIdx.x * blockDim.x + threadIdx.x;
    if (e >= TOTE) return;
    int d = (e < NE) ? ei[NE + e] : (e - NE);
    atomicAdd(&g_count[d], 1);
}

__global__ void scan_kernel() {
    __shared__ int part[1024];
    int t = threadIdx.x;
    const int CH = 98;  // 1024*98 >= NN
    int base = t * CH;
    int s = 0;
    for (int i = 0; i < CH; i++) {
        int idx = base + i;
        if (idx < NN) s += g_count[idx];
    }
    part[t] = s;
    __syncthreads();
    for (int off = 1; off < 1024; off <<= 1) {
        int v = (t >= off) ? part[t - off] : 0;
        __syncthreads();
        part[t] += v;
        __syncthreads();
    }
    int ex = (t == 0) ? 0 : part[t - 1];
    for (int i = 0; i < CH; i++) {
        int idx = base + i;
        if (idx < NN) {
            g_offs[idx] = ex;
            g_cursor[idx] = ex;
            ex += g_count[idx];
        }
    }
    if (t == 0) g_offs[NN] = part[1023];
}

__global__ void scatter_kernel(const int* __restrict__ ei) {
    int e = blockIdx.x * blockDim.x + threadIdx.x;
    if (e >= TOTE) return;
    int d = (e < NE) ? ei[NE + e] : (e - NE);
    int pos = atomicAdd(&g_cursor[d], 1);
    g_perm[pos] = e;
}

// ---------------- x0 = concat(item,user,fet) ----------------
__global__ void build_x0_kernel(const float* __restrict__ a,
                                const float* __restrict__ b,
                                const float* __restrict__ c) {
    int i = blockIdx.x * blockDim.x + threadIdx.x;  // over NN*16 float4
    if (i >= NN * 16) return;
    int v = i >> 4;
    float4 val;
    if (v < NI)            val = ((const float4*)a)[i];
    else if (v < NI + NU)  val = ((const float4*)b)[i - NI * 16];
    else                   val = ((const float4*)c)[i - (NI + NU) * 16];
    ((float4*)g_x0)[i] = val;
}

// ---------------- SGEMM: C[M,NC] = A[M,K] @ B[K,NC] ----------------
// BM=128, BN=64, BK=16, 256 threads, double-buffered smem, FFMA2 inner loop.
template <int K, int NC>
__global__ void __launch_bounds__(256, 2)
sgemm_db(const float* __restrict__ A, const float* __restrict__ B,
         float* __restrict__ C, int M) {
    __shared__ __align__(16) float As[2][16][132];
    __shared__ __align__(16) float Bs[2][16][64];
    const int tid = threadIdx.x;
    const int tr = tid >> 4, tc = tid & 15;
    const int rowBase = blockIdx.x * 128;
    const int colBase = blockIdx.y * 64;
    const int ar0 = tid >> 2;              // 0..63
    const int ar1 = ar0 + 64;              // 64..127
    const int ac  = (tid & 3) * 4;         // 0,4,8,12
    const int br  = tid >> 4, bc = (tid & 15) * 4;
    const int NSTEP = K / 16;

    unsigned long long acc[4][4];
    #pragma unroll
    for (int p = 0; p < 4; p++)
        #pragma unroll
        for (int j = 0; j < 4; j++) acc[p][j] = 0ull;

    // prologue: tile 0 straight to smem buf 0
    {
        float4 va0 = make_float4(0.f, 0.f, 0.f, 0.f), va1 = va0;
        if (rowBase + ar0 < M)
            va0 = *(const float4*)&A[(long)(rowBase + ar0) * K + ac];
        if (rowBase + ar1 < M)
            va1 = *(const float4*)&A[(long)(rowBase + ar1) * K + ac];
        As[0][ac + 0][ar0] = va0.x; As[0][ac + 1][ar0] = va0.y;
        As[0][ac + 2][ar0] = va0.z; As[0][ac + 3][ar0] = va0.w;
        As[0][ac + 0][ar1] = va1.x; As[0][ac + 1][ar1] = va1.y;
        As[0][ac + 2][ar1] = va1.z; As[0][ac + 3][ar1] = va1.w;
        float4 vb = *(const float4*)&B[(long)br * NC + colBase + bc];
        *(float4*)&Bs[0][br][bc] = vb;
    }
    __syncthreads();

    for (int s = 0; s < NSTEP; s++) {
        const int cur = s & 1;
        float4 va0, va1, vb;
        const bool pf = (s + 1 < NSTEP);
        if (pf) {
            int k0 = (s + 1) * 16;
            va0 = make_float4(0.f, 0.f, 0.f, 0.f); va1 = va0;
            if (rowBase + ar0 < M)
                va0 = *(const float4*)&A[(long)(rowBase + ar0) * K + k0 + ac];
            if (rowBase + ar1 < M)
                va1 = *(const float4*)&A[(long)(rowBase + ar1) * K + k0 + ac];
            vb = *(const float4*)&B[(long)(k0 + br) * NC + colBase + bc];
        }
        #pragma unroll
        for (int kk = 0; kk < 16; kk++) {
            ulonglong2 av0 = *(const ulonglong2*)&As[cur][kk][tr * 8];
            ulonglong2 av1 = *(const ulonglong2*)&As[cur][kk][tr * 8 + 4];
            float4 bv = *(const float4*)&Bs[cur][kk][tc * 4];
            unsigned long long bb0 = pk2(bv.x, bv.x);
            unsigned long long bb1 = pk2(bv.y, bv.y);
            unsigned long long bb2 = pk2(bv.z, bv.z);
            unsigned long long bb3 = pk2(bv.w, bv.w);
            unsigned long long ap0 = av0.x, ap1 = av0.y, ap2 = av1.x, ap3 = av1.y;
            fma2(acc[0][0], ap0, bb0); fma2(acc[0][1], ap0, bb1);
            fma2(acc[0][2], ap0, bb2); fma2(acc[0][3], ap0, bb3);
            fma2(acc[1][0], ap1, bb0); fma2(acc[1][1], ap1, bb1);
            fma2(acc[1][2], ap1, bb2); fma2(acc[1][3], ap1, bb3);
            fma2(acc[2][0], ap2, bb0); fma2(acc[2][1], ap2, bb1);
            fma2(acc[2][2], ap2, bb2); fma2(acc[2][3], ap2, bb3);
            fma2(acc[3][0], ap3, bb0); fma2(acc[3][1], ap3, bb1);
            fma2(acc[3][2], ap3, bb2); fma2(acc[3][3], ap3, bb3);
        }
        if (pf) {
            const int nb = 1 - cur;
            As[nb][ac + 0][ar0] = va0.x; As[nb][ac + 1][ar0] = va0.y;
            As[nb][ac + 2][ar0] = va0.z; As[nb][ac + 3][ar0] = va0.w;
            As[nb][ac + 0][ar1] = va1.x; As[nb][ac + 1][ar1] = va1.y;
            As[nb][ac + 2][ar1] = va1.z; As[nb][ac + 3][ar1] = va1.w;
            *(float4*)&Bs[nb][br][bc] = vb;
            __syncthreads();
        }
    }

    #pragma unroll
    for (int p = 0; p < 4; p++) {
        int r0 = rowBase + tr * 8 + 2 * p;
        float l0, h0, l1, h1, l2, h2, l3, h3;
        unpk2(acc[p][0], l0, h0); unpk2(acc[p][1], l1, h1);
        unpk2(acc[p][2], l2, h2); unpk2(acc[p][3], l3, h3);
        if (r0 < M)
            *(float4*)&C[(long)r0 * NC + colBase + tc * 4] =
                make_float4(l0, l1, l2, l3);
        if (r0 + 1 < M)
            *(float4*)&C[(long)(r0 + 1) * NC + colBase + tc * 4] =
                make_float4(h0, h1, h2, h3);
    }
}

// ---------------- attention dots ----------------
template <int HEADS>
__global__ void att_kernel(const float* __restrict__ xw,
                           const float* __restrict__ vs,
                           const float* __restrict__ vd) {
    int w = (blockIdx.x * blockDim.x + threadIdx.x) >> 5;
    if (w >= NN) return;
    int lane = threadIdx.x & 31;
    const int NC = HEADS * 64;
    #pragma unroll
    for (int h = 0; h < HEADS; h++) {
        float xa = xw[(long)w * NC + h * 64 + lane];
        float xb = xw[(long)w * NC + h * 64 + 32 + lane];
        float s = xa * vs[h * 64 + lane] + xb * vs[h * 64 + 32 + lane];
        float d = xa * vd[h * 64 + lane] + xb * vd[h * 64 + 32 + lane];
        #pragma unroll
        for (int o = 16; o; o >>= 1) {
            s += __shfl_xor_sync(0xffffffffu, s, o);
            d += __shfl_xor_sync(0xffffffffu, d, o);
        }
        if (lane == 0) {
            g_asrc[w * HEADS + h] = s;
            g_adst[w * HEADS + h] = d;
        }
    }
}

__device__ __forceinline__ float lrelu(float x) { return x > 0.f ? x : 0.2f * x; }

// ---------------- aggregation, H=2, concat; warp per dst node ----------------
__global__ void agg_h2_kernel(const float* __restrict__ xw,
                              const int* __restrict__ ei,
                              const float* __restrict__ bias,
                              float* __restrict__ hout,
                              float* __restrict__ alpha_out,
                              int mode) {
    int v = (blockIdx.x * blockDim.x + threadIdx.x) >> 5;
    if (v >= NN) return;
    int lane = threadIdx.x & 31;
    int beg = g_offs[v];
    int deg = g_offs[v + 1] - beg;
    float ad0 = g_adst[2 * v], ad1 = g_adst[2 * v + 1];

    // pass 1: online softmax stats (max + denom in one edge sweep)
    float m0 = -3.0e38f, s0 = 0.f, m1 = -3.0e38f, s1 = 0.f;
    for (int i = lane; i < deg; i += 32) {
        int eid = g_perm[beg + i];
        int s = (eid < NE) ? ei[eid] : (eid - NE);
        float e0 = lrelu(g_asrc[2 * s] + ad0);
        float e1 = lrelu(g_asrc[2 * s + 1] + ad1);
        float n0 = fmaxf(m0, e0);
        s0 = s0 * __expf(m0 - n0) + __expf(e0 - n0);
        m0 = n0;
        float n1 = fmaxf(m1, e1);
        s1 = s1 * __expf(m1 - n1) + __expf(e1 - n1);
        m1 = n1;
    }
    #pragma unroll
    for (int o = 16; o; o >>= 1) {
        float om = __shfl_xor_sync(0xffffffffu, m0, o);
        float os = __shfl_xor_sync(0xffffffffu, s0, o);
        float nm = fmaxf(m0, om);
        s0 = s0 * __expf(m0 - nm) + os * __expf(om - nm);
        m0 = nm;
        om = __shfl_xor_sync(0xffffffffu, m1, o);
        os = __shfl_xor_sync(0xffffffffu, s1, o);
        nm = fmaxf(m1, om);
        s1 = s1 * __expf(m1 - nm) + os * __expf(om - nm);
        m1 = nm;
    }
    float inv0 = 1.f / (s0 + 1e-16f);
    float inv1 = 1.f / (s1 + 1e-16f);

    // pass 2: alpha write + weighted feature gather (lane owns 4 features)
    unsigned long long acc01 = 0ull, acc23 = 0ull;
    const ulonglong2* xw2 = (const ulonglong2*)xw;
    for (int base = 0; base < deg; base += 32) {
        int i = base + lane;
        float al0 = 0.f, al1 = 0.f;
        int sidx = 0;
        if (i < deg) {
            int eid = g_perm[beg + i];
            sidx = (eid < NE) ? ei[eid] : (eid - NE);
            float e0 = lrelu(g_asrc[2 * sidx] + ad0);
            float e1 = lrelu(g_asrc[2 * sidx + 1] + ad1);
            al0 = __expf(e0 - m0) * inv0;
            al1 = __expf(e1 - m1) * inv1;
            alpha_out[2 * eid] = al0;
            alpha_out[2 * eid + 1] = al1;
        }
        int cnt = min(32, deg - base);
        int t = 0;
        for (; t + 4 <= cnt; t += 4) {
            int sA = __shfl_sync(0xffffffffu, sidx, t);
            int sB = __shfl_sync(0xffffffffu, sidx, t + 1);
            int sC = __shfl_sync(0xffffffffu, sidx, t + 2);
            int sD = __shfl_sync(0xffffffffu, sidx, t + 3);
            float a0A = __shfl_sync(0xffffffffu, al0, t);
            float a1A = __shfl_sync(0xffffffffu, al1, t);
            float a0B = __shfl_sync(0xffffffffu, al0, t + 1);
            float a1B = __shfl_sync(0xffffffffu, al1, t + 1);
            float a0C = __shfl_sync(0xffffffffu, al0, t + 2);
            float a1C = __shfl_sync(0xffffffffu, al1, t + 2);
            float a0D = __shfl_sync(0xffffffffu, al0, t + 3);
            float a1D = __shfl_sync(0xffffffffu, al1, t + 3);
            ulonglong2 xA = xw2[(long)sA * 32 + lane];
            ulonglong2 xB = xw2[(long)sB * 32 + lane];
            ulonglong2 xC = xw2[(long)sC * 32 + lane];
            ulonglong2 xD = xw2[(long)sD * 32 + lane];
            float aA = (lane < 16) ? a0A : a1A;
            float aB = (lane < 16) ? a0B : a1B;
            float aC = (lane < 16) ? a0C : a1C;
            float aD = (lane < 16) ? a0D : a1D;
            unsigned long long dA = pk2(aA, aA), dB = pk2(aB, aB);
            unsigned long long dC = pk2(aC, aC), dD = pk2(aD, aD);
            fma2(acc01, dA, xA.x); fma2(acc23, dA, xA.y);
            fma2(acc01, dB, xB.x); fma2(acc23, dB, xB.y);
            fma2(acc01, dC, xC.x); fma2(acc23, dC, xC.y);
            fma2(acc01, dD, xD.x); fma2(acc23, dD, xD.y);
        }
        for (; t < cnt; t++) {
            int sA = __shfl_sync(0xffffffffu, sidx, t);
            float a0A = __shfl_sync(0xffffffffu, al0, t);
            float a1A = __shfl_sync(0xffffffffu, al1, t);
            ulonglong2 xA = xw2[(long)sA * 32 + lane];
            float aA = (lane < 16) ? a0A : a1A;
            unsigned long long dA = pk2(aA, aA);
            fma2(acc01, dA, xA.x); fma2(acc23, dA, xA.y);
        }
    }

    // epilogue
    float xa, xb, xc, xd;
    unpk2(acc01, xa, xb);
    unpk2(acc23, xc, xd);
    int f = lane * 4;
    xa += bias[f]; xb += bias[f + 1]; xc += bias[f + 2]; xd += bias[f + 3];
    float4 hv = make_float4(fmaxf(xa, 0.f), fmaxf(xb, 0.f),
                            fmaxf(xc, 0.f), fmaxf(xd, 0.f));
    ((float4*)hout)[(long)v * 32 + lane] = hv;

    float pa = __shfl_xor_sync(0xffffffffu, xa, 16);
    float pb = __shfl_xor_sync(0xffffffffu, xb, 16);
    float pc = __shfl_xor_sync(0xffffffffu, xc, 16);
    float pd = __shfl_xor_sync(0xffffffffu, xd, 16);
    if (lane < 16) {
        float4 ev = make_float4(0.5f * (xa + pa), 0.5f * (xb + pb),
                                0.5f * (xc + pc), 0.5f * (xd + pd));
        long fidx = (long)v * 16 + lane;
        if (mode == 1) {
            float4 xv = ((const float4*)g_x0)[fidx];
            ev.x += xv.x; ev.y += xv.y; ev.z += xv.z; ev.w += xv.w;
        } else {
            float4 fv = ((const float4*)g_facc)[fidx];
            ev.x += fv.x; ev.y += fv.y; ev.z += fv.z; ev.w += fv.w;
        }
        ((float4*)g_facc)[fidx] = ev;
    }
}

// ---------------- aggregation, H=1 (layer 3) + final outputs ----------------
__global__ void agg_h1_kernel(const float* __restrict__ xw,
                              const int* __restrict__ ei,
                              const float* __restrict__ bias,
                              float* __restrict__ out) {
    int v = (blockIdx.x * blockDim.x + threadIdx.x) >> 5;
    if (v >= NN) return;
    int lane = threadIdx.x & 31;
    int beg = g_offs[v];
    int deg = g_offs[v + 1] - beg;
    float ad = g_adst[v];

    float m = -3.0e38f, ssum = 0.f;
    for (int i = lane; i < deg; i += 32) {
        int eid = g_perm[beg + i];
        int s = (eid < NE) ? ei[eid] : (eid - NE);
        float e = lrelu(g_asrc[s] + ad);
        float n = fmaxf(m, e);
        ssum = ssum * __expf(m - n) + __expf(e - n);
        m = n;
    }
    #pragma unroll
    for (int o = 16; o; o >>= 1) {
        float om = __shfl_xor_sync(0xffffffffu, m, o);
        float os = __shfl_xor_sync(0xffffffffu, ssum, o);
        float nm = fmaxf(m, om);
        ssum = ssum * __expf(m - nm) + os * __expf(om - nm);
        m = nm;
    }
    float inv = 1.f / (ssum + 1e-16f);

    unsigned long long acc = 0ull;
    const unsigned long long* xw1 = (const unsigned long long*)xw;
    for (int base = 0; base < deg; base += 32) {
        int i = base + lane;
        float al = 0.f;
        int sidx = 0;
        if (i < deg) {
            int eid = g_perm[beg + i];
            sidx = (eid < NE) ? ei[eid] : (eid - NE);
            al = __expf(lrelu(g_asrc[sidx] + ad) - m) * inv;
            out[A3OFF + eid] = al;
        }
        int cnt = min(32, deg - base);
        int t = 0;
        for (; t + 4 <= cnt; t += 4) {
            int sA = __shfl_sync(0xffffffffu, sidx, t);
            int sB = __shfl_sync(0xffffffffu, sidx, t + 1);
            int sC = __shfl_sync(0xffffffffu, sidx, t + 2);
            int sD = __shfl_sync(0xffffffffu, sidx, t + 3);
            float aA = __shfl_sync(0xffffffffu, al, t);
            float aB = __shfl_sync(0xffffffffu, al, t + 1);
            float aC = __shfl_sync(0xffffffffu, al, t + 2);
            float aD = __shfl_sync(0xffffffffu, al, t + 3);
            unsigned long long xA = xw1[(long)sA * 32 + lane];
            unsigned long long xB = xw1[(long)sB * 32 + lane];
            unsigned long long xC = xw1[(long)sC * 32 + lane];
            unsigned long long xD = xw1[(long)sD * 32 + lane];
            fma2(acc, pk2(aA, aA), xA);
            fma2(acc, pk2(aB, aB), xB);
            fma2(acc, pk2(aC, aC), xC);
            fma2(acc, pk2(aD, aD), xD);
        }
        for (; t < cnt; t++) {
            int sA = __shfl_sync(0xffffffffu, sidx, t);
            float aA = __shfl_sync(0xffffffffu, al, t);
            unsigned long long xA = xw1[(long)sA * 32 + lane];
            fma2(acc, pk2(aA, aA), xA);
        }
    }

    float xa, xb;
    unpk2(acc, xa, xb);
    int f = lane * 2;
    xa += bias[f]; xb += bias[f + 1];
    float fa = (g_facc[(long)v * 64 + f] + xa) * 0.25f;
    float fb = (g_facc[(long)v * 64 + f + 1] + xb) * 0.25f;
    out[FINALO + (long)v * 64 + f] = fa;
    out[FINALO + (long)v * 64 + f + 1] = fb;
    long seg;
    if (v < NI)            seg = ITEMO + (long)v * 64;
    else if (v < NI + NU)  seg = USERO + (long)(v - NI) * 64;
    else                   seg = FETO + (long)(v - NI - NU) * 64;
    out[seg + f] = fa;
    out[seg + f + 1] = fb;
}

// ---------------- host launch ----------------
extern "C" void kernel_launch(void* const* d_in, const int* in_sizes, int n_in,
                              void* d_out, int out_size) {
    const int*   ei       = (const int*)d_in[0];
    const float* emb_item = (const float*)d_in[1];
    const float* emb_user = (const float*)d_in[2];
    const float* emb_fet  = (const float*)d_in[3];
    const float* W1  = (const float*)d_in[4];
    const float* as1 = (const float*)d_in[5];
    const float* ad1 = (const float*)d_in[6];
    const float* b1  = (const float*)d_in[7];
    const float* W2  = (const float*)d_in[8];
    const float* as2 = (const float*)d_in[9];
    const float* ad2 = (const float*)d_in[10];
    const float* b2  = (const float*)d_in[11];
    const float* W3  = (const float*)d_in[12];
    const float* as3 = (const float*)d_in[13];
    const float* ad3 = (const float*)d_in[14];
    const float* b3  = (const float*)d_in[15];
    float* out = (float*)d_out;

    float *x0p, *xwp, *hp;
    cudaGetSymbolAddress((void**)&x0p, g_x0);
    cudaGetSymbolAddress((void**)&xwp, g_xw);
    cudaGetSymbolAddress((void**)&hp, g_h);

    const int T = 256;
    int nodeBlocks = (NN + T - 1) / T;
    int edgeBlocks = (TOTE + T - 1) / T;
    int warpBlocks = (NN * 32 + T - 1) / T;  // one warp per node

    // CSR build
    zero_count_kernel<<<nodeBlocks, T>>>();
    hist_kernel<<<edgeBlocks, T>>>(ei);
    scan_kernel<<<1, 1024>>>();
    scatter_kernel<<<edgeBlocks, T>>>(ei);

    // x0 concat
    build_x0_kernel<<<(NN * 16 + T - 1) / T, T>>>(emb_item, emb_user, emb_fet);

    // layer 1
    {
        dim3 g((NN + 127) / 128, 2);
        sgemm_db<64, 128><<<g, T>>>(x0p, W1, xwp, NN);
    }
    att_kernel<2><<<warpBlocks, T>>>(xwp, as1, ad1);
    agg_h2_kernel<<<warpBlocks, T>>>(xwp, ei, b1, hp, out + A1OFF, 1);

    // layer 2
    {
        dim3 g((NN + 127) / 128, 2);
        sgemm_db<128, 128><<<g, T>>>(hp, W2, xwp, NN);
    }
    att_kernel<2><<<warpBlocks, T>>>(xwp, as2, ad2);
    agg_h2_kernel<<<warpBlocks, T>>>(xwp, ei, b2, hp, out + A2OFF, 2);

    // layer 3
    {
        dim3 g((NN + 127) / 128, 1);
        sgemm_db<128, 64><<<g, T>>>(hp, W3, xwp, NN);
    }
    att_kernel<1><<<warpBlocks, T>>>(xwp, as3, ad3);
    agg_h1_kernel<<<warpBlocks, T>>>(xwp, ei, b3, out);
}

// round 3
// speedup vs baseline: 1.3946x; 1.2049x over previous
#include <cuda_runtime.h>
#include <cuda_bf16.h>

// ---------------- problem constants ----------------
#define NE    1200000   // raw edges
#define NN    100000    // nodes
#define TOTE  1300000   // edges + self loops
#define NI    40000
#define NU    30000
#define NF    30000

// d_out layout (float32), in reference return order
#define ITEMO  0
#define USERO  2560000
#define FETO   4480000
#define FINALO 6400000
#define A1OFF  12800000
#define A2OFF  15400000
#define A3OFF  18000000

#define SCAN_NB 392   // 392*256 = 100352 >= NN

// ---------------- device scratch (no allocations allowed) ----------------
__device__ float g_x0[NN * 64];
__device__ float g_xw[NN * 128];
__device__ float g_h[NN * 128];
__device__ float g_facc[NN * 64];
__device__ float g_asrc[NN * 2];
__device__ float g_adst[NN * 2];
__device__ int   g_count[NN];
__device__ int   g_offs[NN + 1];
__device__ int   g_cursor[NN];
__device__ int   g_perm[TOTE];
__device__ int   g_srcs[TOTE];
__device__ int   g_part[SCAN_NB];
__device__ int   g_partx[SCAN_NB];

// ---------------- f32x2 packed helpers (SASS FFMA2 path) ----------------
__device__ __forceinline__ unsigned long long pk2(float x, float y) {
    unsigned long long r;
    asm("mov.b64 %0, {%1, %2};" : "=l"(r)
        : "r"(__float_as_uint(x)), "r"(__float_as_uint(y)));
    return r;
}
__device__ __forceinline__ void fma2(unsigned long long& d,
                                     unsigned long long a,
                                     unsigned long long b) {
    asm("fma.rn.f32x2 %0, %1, %2, %0;" : "+l"(d) : "l"(a), "l"(b));
}
__device__ __forceinline__ void unpk2(unsigned long long v, float& lo, float& hi) {
    unsigned a, b;
    asm("mov.b64 {%0, %1}, %2;" : "=r"(a), "=r"(b) : "l"(v));
    lo = __uint_as_float(a);
    hi = __uint_as_float(b);
}

// ---------------- CSR build ----------------
__global__ void zero_count_kernel() {
    int i = blockIdx.x * blockDim.x + threadIdx.x;
    if (i < NN) g_count[i] = 0;
}

__global__ void hist_kernel(const int* __restrict__ ei) {
    int e = blockIdx.x * blockDim.x + threadIdx.x;
    if (e >= TOTE) return;
    int d = (e < NE) ? ei[NE + e] : (e - NE);
    atomicAdd(&g_count[d], 1);
}

// three-kernel parallel exclusive scan over g_count -> g_offs/g_cursor
__global__ void scan_part_kernel() {
    __shared__ int sh[256];
    int t = threadIdx.x;
    int i = blockIdx.x * 256 + t;
    int c = (i < NN) ? g_count[i] : 0;
    sh[t] = c;
    __syncthreads();
    #pragma unroll
    for (int off = 128; off; off >>= 1) {
        if (t < off) sh[t] += sh[t + off];
        __syncthreads();
    }
    if (t == 0) g_part[blockIdx.x] = sh[0];
}

__global__ void scan_top_kernel() {
    __shared__ int sh[512];
    int t = threadIdx.x;
    int v = (t < SCAN_NB) ? g_part[t] : 0;
    sh[t] = v;
    __syncthreads();
    for (int off = 1; off < 512; off <<= 1) {
        int u = (t >= off) ? sh[t - off] : 0;
        __syncthreads();
        sh[t] += u;
        __syncthreads();
    }
    if (t < SCAN_NB) g_partx[t] = sh[t] - v;  // exclusive
}

__global__ void scan_fix_kernel() {
    __shared__ int sh[256];
    int t = threadIdx.x;
    int i = blockIdx.x * 256 + t;
    int c = (i < NN) ? g_count[i] : 0;
    sh[t] = c;
    __syncthreads();
    for (int off = 1; off < 256; off <<= 1) {
        int u = (t >= off) ? sh[t - off] : 0;
        __syncthreads();
        sh[t] += u;
        __syncthreads();
    }
    int base = g_partx[blockIdx.x];
    int ex = base + sh[t] - c;
    if (i < NN) {
        g_offs[i] = ex;
        g_cursor[i] = ex;
    }
    if (i == NN - 1) g_offs[NN] = base + sh[t];
}

__global__ void scatter_kernel(const int* __restrict__ ei) {
    int e = blockIdx.x * blockDim.x + threadIdx.x;
    if (e >= TOTE) return;
    int d, s;
    if (e < NE) {
        s = ei[e];
        d = ei[NE + e];
    } else {
        s = e - NE;
        d = e - NE;
    }
    int pos = atomicAdd(&g_cursor[d], 1);
    g_perm[pos] = e;
    g_srcs[pos] = s;
}

// ---------------- x0 = concat(item,user,fet); also init facc = x0 ----------------
__global__ void build_x0_kernel(const float* __restrict__ a,
                                const float* __restrict__ b,
                                const float* __restrict__ c) {
    int i = blockIdx.x * blockDim.x + threadIdx.x;  // over NN*16 float4
    if (i >= NN * 16) return;
    int v = i >> 4;
    float4 val;
    if (v < NI)            val = ((const float4*)a)[i];
    else if (v < NI + NU)  val = ((const float4*)b)[i - NI * 16];
    else                   val = ((const float4*)c)[i - (NI + NU) * 16];
    ((float4*)g_x0)[i] = val;
    ((float4*)g_facc)[i] = val;
}

// ---------------- SGEMM + fused attention dots ----------------
// C[M,NC] = A[M,K] @ B[K,NC]; BM=128, BN=64, BK=16, 256 threads,
// double-buffered smem, FFMA2 inner loop. Epilogue computes
// g_asrc/g_adst[row*AS + head] where head = blockIdx.y (64-col block = 1 head).
template <int K, int NC, int AS>
__global__ void __launch_bounds__(256, 2)
sgemm_att(const float* __restrict__ A, const float* __restrict__ B,
          float* __restrict__ C, int M,
          const float* __restrict__ vs, const float* __restrict__ vd) {
    __shared__ __align__(16) float As[2][16][132];
    __shared__ __align__(16) float Bs[2][16][64];
    const int tid = threadIdx.x;
    const int tr = tid >> 4, tc = tid & 15;
    const int rowBase = blockIdx.x * 128;
    const int colBase = blockIdx.y * 64;
    const int ar0 = tid >> 2;
    const int ar1 = ar0 + 64;
    const int ac  = (tid & 3) * 4;
    const int br  = tid >> 4, bc = (tid & 15) * 4;
    const int NSTEP = K / 16;

    unsigned long long acc[4][4];
    #pragma unroll
    for (int p = 0; p < 4; p++)
        #pragma unroll
        for (int j = 0; j < 4; j++) acc[p][j] = 0ull;

    {
        float4 va0 = make_float4(0.f, 0.f, 0.f, 0.f), va1 = va0;
        if (rowBase + ar0 < M)
            va0 = *(const float4*)&A[(long)(rowBase + ar0) * K + ac];
        if (rowBase + ar1 < M)
            va1 = *(const float4*)&A[(long)(rowBase + ar1) * K + ac];
        As[0][ac + 0][ar0] = va0.x; As[0][ac + 1][ar0] = va0.y;
        As[0][ac + 2][ar0] = va0.z; As[0][ac + 3][ar0] = va0.w;
        As[0][ac + 0][ar1] = va1.x; As[0][ac + 1][ar1] = va1.y;
        As[0][ac + 2][ar1] = va1.z; As[0][ac + 3][ar1] = va1.w;
        float4 vb = *(const float4*)&B[(long)br * NC + colBase + bc];
        *(float4*)&Bs[0][br][bc] = vb;
    }
    __syncthreads();

    for (int s = 0; s < NSTEP; s++) {
        const int cur = s & 1;
        float4 va0, va1, vb;
        const bool pf = (s + 1 < NSTEP);
        if (pf) {
            int k0 = (s + 1) * 16;
            va0 = make_float4(0.f, 0.f, 0.f, 0.f); va1 = va0;
            if (rowBase + ar0 < M)
                va0 = *(const float4*)&A[(long)(rowBase + ar0) * K + k0 + ac];
            if (rowBase + ar1 < M)
                va1 = *(const float4*)&A[(long)(rowBase + ar1) * K + k0 + ac];
            vb = *(const float4*)&B[(long)(k0 + br) * NC + colBase + bc];
        }
        #pragma unroll
        for (int kk = 0; kk < 16; kk++) {
            ulonglong2 av0 = *(const ulonglong2*)&As[cur][kk][tr * 8];
            ulonglong2 av1 = *(const ulonglong2*)&As[cur][kk][tr * 8 + 4];
            float4 bv = *(const float4*)&Bs[cur][kk][tc * 4];
            unsigned long long bb0 = pk2(bv.x, bv.x);
            unsigned long long bb1 = pk2(bv.y, bv.y);
            unsigned long long bb2 = pk2(bv.z, bv.z);
            unsigned long long bb3 = pk2(bv.w, bv.w);
            unsigned long long ap0 = av0.x, ap1 = av0.y, ap2 = av1.x, ap3 = av1.y;
            fma2(acc[0][0], ap0, bb0); fma2(acc[0][1], ap0, bb1);
            fma2(acc[0][2], ap0, bb2); fma2(acc[0][3], ap0, bb3);
            fma2(acc[1][0], ap1, bb0); fma2(acc[1][1], ap1, bb1);
            fma2(acc[1][2], ap1, bb2); fma2(acc[1][3], ap1, bb3);
            fma2(acc[2][0], ap2, bb0); fma2(acc[2][1], ap2, bb1);
            fma2(acc[2][2], ap2, bb2); fma2(acc[2][3], ap2, bb3);
            fma2(acc[3][0], ap3, bb0); fma2(acc[3][1], ap3, bb1);
            fma2(acc[3][2], ap3, bb2); fma2(acc[3][3], ap3, bb3);
        }
        if (pf) {
            const int nb = 1 - cur;
            As[nb][ac + 0][ar0] = va0.x; As[nb][ac + 1][ar0] = va0.y;
            As[nb][ac + 2][ar0] = va0.z; As[nb][ac + 3][ar0] = va0.w;
            As[nb][ac + 0][ar1] = va1.x; As[nb][ac + 1][ar1] = va1.y;
            As[nb][ac + 2][ar1] = va1.z; As[nb][ac + 3][ar1] = va1.w;
            *(float4*)&Bs[nb][br][bc] = vb;
            __syncthreads();
        }
    }

    // unpack: rows tr*8+q (q=0..7), cols colBase + tc*4 + j
    float r[8][4];
    #pragma unroll
    for (int p = 0; p < 4; p++)
        #pragma unroll
        for (int j = 0; j < 4; j++)
            unpk2(acc[p][j], r[2 * p][j], r[2 * p + 1][j]);

    #pragma unroll
    for (int q = 0; q < 8; q++) {
        int row = rowBase + tr * 8 + q;
        if (row < M)
            *(float4*)&C[(long)row * NC + colBase + tc * 4] =
                make_float4(r[q][0], r[q][1], r[q][2], r[q][3]);
    }

    // fused attention dots: reduce over the 64 cols of this head
    float vsv[4], vdv[4];
    #pragma unroll
    for (int j = 0; j < 4; j++) {
        vsv[j] = vs[colBase + tc * 4 + j];
        vdv[j] = vd[colBase + tc * 4 + j];
    }
    const int head = blockIdx.y;
    #pragma unroll
    for (int q = 0; q < 8; q++) {
        float sdot = r[q][0] * vsv[0] + r[q][1] * vsv[1] +
                     r[q][2] * vsv[2] + r[q][3] * vsv[3];
        float ddot = r[q][0] * vdv[0] + r[q][1] * vdv[1] +
                     r[q][2] * vdv[2] + r[q][3] * vdv[3];
        #pragma unroll
        for (int off = 8; off; off >>= 1) {
            sdot += __shfl_xor_sync(0xffffffffu, sdot, off);
            ddot += __shfl_xor_sync(0xffffffffu, ddot, off);
        }
        int row = rowBase + tr * 8 + q;
        if (tc == 0 && row < M) {
            g_asrc[(long)row * AS + head] = sdot;
            g_adst[(long)row * AS + head] = ddot;
        }
    }
}

__device__ __forceinline__ float lrelu(float x) { return x > 0.f ? x : 0.2f * x; }

// ---------------- aggregation, H=2: one warp per (node, head) ----------------
__global__ void agg_h2_kernel(const float* __restrict__ xw,
                              const float* __restrict__ bias,
                              float* __restrict__ hout,
                              float* __restrict__ alpha_out) {
    int gw = (blockIdx.x * blockDim.x + threadIdx.x) >> 5;
    if (gw >= 2 * NN) return;
    int v = gw >> 1, h = gw & 1;
    int lane = threadIdx.x & 31;
    int beg = g_offs[v];
    int deg = g_offs[v + 1] - beg;
    float ad = g_adst[2 * v + h];

    // pass 1: online softmax stats (lane-strided)
    float m = -3.0e38f, ssum = 0.f;
    for (int i = lane; i < deg; i += 32) {
        int sc = g_srcs[beg + i];
        float e = lrelu(g_asrc[2 * sc + h] + ad);
        float n = fmaxf(m, e);
        ssum = ssum * __expf(m - n) + __expf(e - n);
        m = n;
    }
    #pragma unroll
    for (int o = 16; o; o >>= 1) {
        float om = __shfl_xor_sync(0xffffffffu, m, o);
        float os = __shfl_xor_sync(0xffffffffu, ssum, o);
        float nm = fmaxf(m, om);
        ssum = ssum * __expf(m - nm) + os * __expf(om - nm);
        m = nm;
    }
    float inv = 1.f / (ssum + 1e-16f);

    // pass 2: alpha write + weighted feature gather (lane owns 2 feats of head h)
    unsigned long long acc = 0ull;
    const unsigned long long* xh = (const unsigned long long*)xw;
    const long hoff = h * 32 + lane;
    for (int base = 0; base < deg; base += 32) {
        int i = base + lane;
        float al = 0.f;
        int sidx = 0;
        if (i < deg) {
            sidx = g_srcs[beg + i];
            al = __expf(lrelu(g_asrc[2 * sidx + h] + ad) - m) * inv;
            int eid = g_perm[beg + i];
            alpha_out[2 * eid + h] = al;
        }
        int cnt = min(32, deg - base);
        int t = 0;
        for (; t + 4 <= cnt; t += 4) {
            int sA = __shfl_sync(0xffffffffu, sidx, t);
            int sB = __shfl_sync(0xffffffffu, sidx, t + 1);
            int sC = __shfl_sync(0xffffffffu, sidx, t + 2);
            int sD = __shfl_sync(0xffffffffu, sidx, t + 3);
            float aA = __shfl_sync(0xffffffffu, al, t);
            float aB = __shfl_sync(0xffffffffu, al, t + 1);
            float aC = __shfl_sync(0xffffffffu, al, t + 2);
            float aD = __shfl_sync(0xffffffffu, al, t + 3);
            unsigned long long xA = xh[(long)sA * 64 + hoff];
            unsigned long long xB = xh[(long)sB * 64 + hoff];
            unsigned long long xC = xh[(long)sC * 64 + hoff];
            unsigned long long xD = xh[(long)sD * 64 + hoff];
            fma2(acc, pk2(aA, aA), xA);
            fma2(acc, pk2(aB, aB), xB);
            fma2(acc, pk2(aC, aC), xC);
            fma2(acc, pk2(aD, aD), xD);
        }
        for (; t < cnt; t++) {
            int sA = __shfl_sync(0xffffffffu, sidx, t);
            float aA = __shfl_sync(0xffffffffu, al, t);
            unsigned long long xA = xh[(long)sA * 64 + hoff];
            fma2(acc, pk2(aA, aA), xA);
        }
    }

    // epilogue
    float xa, xb;
    unpk2(acc, xa, xb);
    int f = h * 64 + lane * 2;
    xa += bias[f];
    xb += bias[f + 1];
    ((float2*)hout)[(long)v * 64 + h * 32 + lane] =
        make_float2(fmaxf(xa, 0.f), fmaxf(xb, 0.f));
    // facc += 0.5 * x  (head-mean contribution)
    atomicAdd(&g_facc[(long)v * 64 + lane * 2], 0.5f * xa);
    atomicAdd(&g_facc[(long)v * 64 + lane * 2 + 1], 0.5f * xb);
}

// ---------------- aggregation, H=1 (layer 3) + final outputs ----------------
__global__ void agg_h1_kernel(const float* __restrict__ xw,
                              const float* __restrict__ bias,
                              float* __restrict__ out) {
    int v = (blockIdx.x * blockDim.x + threadIdx.x) >> 5;
    if (v >= NN) return;
    int lane = threadIdx.x & 31;
    int beg = g_offs[v];
    int deg = g_offs[v + 1] - beg;
    float ad = g_adst[v];

    float m = -3.0e38f, ssum = 0.f;
    for (int i = lane; i < deg; i += 32) {
        int sc = g_srcs[beg + i];
        float e = lrelu(g_asrc[sc] + ad);
        float n = fmaxf(m, e);
        ssum = ssum * __expf(m - n) + __expf(e - n);
        m = n;
    }
    #pragma unroll
    for (int o = 16; o; o >>= 1) {
        float om = __shfl_xor_sync(0xffffffffu, m, o);
        float os = __shfl_xor_sync(0xffffffffu, ssum, o);
        float nm = fmaxf(m, om);
        ssum = ssum * __expf(m - nm) + os * __expf(om - nm);
        m = nm;
    }
    float inv = 1.f / (ssum + 1e-16f);

    unsigned long long acc = 0ull;
    const unsigned long long* xw1 = (const unsigned long long*)xw;
    for (int base = 0; base < deg; base += 32) {
        int i = base + lane;
        float al = 0.f;
        int sidx = 0;
        if (i < deg) {
            sidx = g_srcs[beg + i];
            al = __expf(lrelu(g_asrc[sidx] + ad) - m) * inv;
            int eid = g_perm[beg + i];
            out[A3OFF + eid] = al;
        }
        int cnt = min(32, deg - base);
        int t = 0;
        for (; t + 4 <= cnt; t += 4) {
            int sA = __shfl_sync(0xffffffffu, sidx, t);
            int sB = __shfl_sync(0xffffffffu, sidx, t + 1);
            int sC = __shfl_sync(0xffffffffu, sidx, t + 2);
            int sD = __shfl_sync(0xffffffffu, sidx, t + 3);
            float aA = __shfl_sync(0xffffffffu, al, t);
            float aB = __shfl_sync(0xffffffffu, al, t + 1);
            float aC = __shfl_sync(0xffffffffu, al, t + 2);
            float aD = __shfl_sync(0xffffffffu, al, t + 3);
            unsigned long long xA = xw1[(long)sA * 32 + lane];
            unsigned long long xB = xw1[(long)sB * 32 + lane];
            unsigned long long xC = xw1[(long)sC * 32 + lane];
            unsigned long long xD = xw1[(long)sD * 32 + lane];
            fma2(acc, pk2(aA, aA), xA);
            fma2(acc, pk2(aB, aB), xB);
            fma2(acc, pk2(aC, aC), xC);
            fma2(acc, pk2(aD, aD), xD);
        }
        for (; t < cnt; t++) {
            int sA = __shfl_sync(0xffffffffu, sidx, t);
            float aA = __shfl_sync(0xffffffffu, al, t);
            unsigned long long xA = xw1[(long)sA * 32 + lane];
            fma2(acc, pk2(aA, aA), xA);
        }
    }

    float xa, xb;
    unpk2(acc, xa, xb);
    int f = lane * 2;
    xa += bias[f];
    xb += bias[f + 1];
    float fa = (g_facc[(long)v * 64 + f] + xa) * 0.25f;
    float fb = (g_facc[(long)v * 64 + f + 1] + xb) * 0.25f;
    out[FINALO + (long)v * 64 + f] = fa;
    out[FINALO + (long)v * 64 + f + 1] = fb;
    long seg;
    if (v < NI)            seg = ITEMO + (long)v * 64;
    else if (v < NI + NU)  seg = USERO + (long)(v - NI) * 64;
    else                   seg = FETO + (long)(v - NI - NU) * 64;
    out[seg + f] = fa;
    out[seg + f + 1] = fb;
}

// ---------------- host launch ----------------
extern "C" void kernel_launch(void* const* d_in, const int* in_sizes, int n_in,
                              void* d_out, int out_size) {
    const int*   ei       = (const int*)d_in[0];
    const float* emb_item = (const float*)d_in[1];
    const float* emb_user = (const float*)d_in[2];
    const float* emb_fet  = (const float*)d_in[3];
    const float* W1  = (const float*)d_in[4];
    const float* as1 = (const float*)d_in[5];
    const float* ad1 = (const float*)d_in[6];
    const float* b1  = (const float*)d_in[7];
    const float* W2  = (const float*)d_in[8];
    const float* as2 = (const float*)d_in[9];
    const float* ad2 = (const float*)d_in[10];
    const float* b2  = (const float*)d_in[11];
    const float* W3  = (const float*)d_in[12];
    const float* as3 = (const float*)d_in[13];
    const float* ad3 = (const float*)d_in[14];
    const float* b3  = (const float*)d_in[15];
    float* out = (float*)d_out;

    float *x0p, *xwp, *hp;
    cudaGetSymbolAddress((void**)&x0p, g_x0);
    cudaGetSymbolAddress((void**)&xwp, g_xw);
    cudaGetSymbolAddress((void**)&hp, g_h);

    const int T = 256;
    int nodeBlocks = (NN + T - 1) / T;
    int edgeBlocks = (TOTE + T - 1) / T;
    int warpBlocks = (NN * 32 + T - 1) / T;       // one warp per node
    int warp2Blocks = (2 * NN * 32 + T - 1) / T;  // one warp per (node, head)

    // CSR build
    zero_count_kernel<<<nodeBlocks, T>>>();
    hist_kernel<<<edgeBlocks, T>>>(ei);
    scan_part_kernel<<<SCAN_NB, 256>>>();
    scan_top_kernel<<<1, 512>>>();
    scan_fix_kernel<<<SCAN_NB, 256>>>();
    scatter_kernel<<<edgeBlocks, T>>>(ei);

    // x0 concat + facc init
    build_x0_kernel<<<(NN * 16 + T - 1) / T, T>>>(emb_item, emb_user, emb_fet);

    // layer 1
    {
        dim3 g((NN + 127) / 128, 2);
        sgemm_att<64, 128, 2><<<g, T>>>(x0p, W1, xwp, NN, as1, ad1);
    }
    agg_h2_kernel<<<warp2Blocks, T>>>(xwp, b1, hp, out + A1OFF);

    // layer 2
    {
        dim3 g((NN + 127) / 128, 2);
        sgemm_att<128, 128, 2><<<g, T>>>(hp, W2, xwp, NN, as2, ad2);
    }
    agg_h2_kernel<<<warp2Blocks, T>>>(xwp, b2, hp, out + A2OFF);

    // layer 3
    {
        dim3 g((NN + 127) / 128, 1);
        sgemm_att<128, 64, 1><<<g, T>>>(hp, W3, xwp, NN, as3, ad3);
    }
    agg_h1_kernel<<<warpBlocks, T>>>(xwp, b3, out);
}

// round 5
// speedup vs baseline: 1.4032x; 1.0061x over previous
#include <cuda_runtime.h>
#include <cuda_bf16.h>

// ---------------- problem constants ----------------
#define NE    1200000   // raw edges
#define NN    100000    // nodes
#define TOTE  1300000   // edges + self loops
#define NI    40000
#define NU    30000
#define NF    30000

// d_out layout (float32), in reference return order
#define ITEMO  0
#define USERO  2560000
#define FETO   4480000
#define FINALO 6400000
#define A1OFF  12800000
#define A2OFF  15400000
#define A3OFF  18000000

#define SCAN_NB 392   // 392*256 = 100352 >= NN

// ---------------- device scratch (no allocations allowed) ----------------
__device__ __align__(16) float g_xw[NN * 128];
__device__ __align__(16) float g_h[NN * 128];
__device__ __align__(16) float g_facc[NN * 64];
__device__ __align__(8)  float g_asrc[NN * 2];
__device__ __align__(8)  float g_adst[NN * 2];
__device__ __align__(16) float4 g_dstat[NN * 2];   // (a_dst, m, inv, _) per (node, head)
__device__ int   g_count[NN];
__device__ int   g_offs[NN + 1];
__device__ int   g_cursor[NN];
__device__ int   g_srcs[TOTE];
__device__ int   g_part[SCAN_NB];
__device__ int   g_partx[SCAN_NB];

// ---------------- f32x2 packed helpers (SASS FFMA2 path) ----------------
__device__ __forceinline__ unsigned long long pk2(float x, float y) {
    unsigned long long r;
    asm("mov.b64 %0, {%1, %2};" : "=l"(r)
        : "r"(__float_as_uint(x)), "r"(__float_as_uint(y)));
    return r;
}
__device__ __forceinline__ void fma2(unsigned long long& d,
                                     unsigned long long a,
                                     unsigned long long b) {
    asm("fma.rn.f32x2 %0, %1, %2, %0;" : "+l"(d) : "l"(a), "l"(b));
}
__device__ __forceinline__ void unpk2(unsigned long long v, float& lo, float& hi) {
    unsigned a, b;
    asm("mov.b64 {%0, %1}, %2;" : "=r"(a), "=r"(b) : "l"(v));
    lo = __uint_as_float(a);
    hi = __uint_as_float(b);
}

// ---------------- CSR build ----------------
__global__ void zero_count_kernel() {
    int i = blockIdx.x * blockDim.x + threadIdx.x;
    if (i < NN) g_count[i] = 0;
}

__global__ void hist_kernel(const int* __restrict__ ei) {
    int e = blockIdx.x * blockDim.x + threadIdx.x;
    if (e >= TOTE) return;
    int d = (e < NE) ? ei[NE + e] : (e - NE);
    atomicAdd(&g_count[d], 1);
}

__global__ void scan_part_kernel() {
    __shared__ int sh[256];
    int t = threadIdx.x;
    int i = blockIdx.x * 256 + t;
    int c = (i < NN) ? g_count[i] : 0;
    sh[t] = c;
    __syncthreads();
    #pragma unroll
    for (int off = 128; off; off >>= 1) {
        if (t < off) sh[t] += sh[t + off];
        __syncthreads();
    }
    if (t == 0) g_part[blockIdx.x] = sh[0];
}

__global__ void scan_top_kernel() {
    __shared__ int sh[512];
    int t = threadIdx.x;
    int v = (t < SCAN_NB) ? g_part[t] : 0;
    sh[t] = v;
    __syncthreads();
    for (int off = 1; off < 512; off <<= 1) {
        int u = (t >= off) ? sh[t - off] : 0;
        __syncthreads();
        sh[t] += u;
        __syncthreads();
    }
    if (t < SCAN_NB) g_partx[t] = sh[t] - v;
}

__global__ void scan_fix_kernel() {
    __shared__ int sh[256];
    int t = threadIdx.x;
    int i = blockIdx.x * 256 + t;
    int c = (i < NN) ? g_count[i] : 0;
    sh[t] = c;
    __syncthreads();
    for (int off = 1; off < 256; off <<= 1) {
        int u = (t >= off) ? sh[t - off] : 0;
        __syncthreads();
        sh[t] += u;
        __syncthreads();
    }
    int base = g_partx[blockIdx.x];
    int ex = base + sh[t] - c;
    if (i < NN) {
        g_offs[i] = ex;
        g_cursor[i] = ex;
    }
    if (i == NN - 1) g_offs[NN] = base + sh[t];
}

__global__ void scatter_kernel(const int* __restrict__ ei) {
    int e = blockIdx.x * blockDim.x + threadIdx.x;
    if (e >= TOTE) return;
    int d, s;
    if (e < NE) {
        s = ei[e];
        d = ei[NE + e];
    } else {
        s = e - NE;
        d = e - NE;
    }
    int pos = atomicAdd(&g_cursor[d], 1);
    g_srcs[pos] = s;
}

// ---------------- facc = x0 = concat(item,user,fet) ----------------
__global__ void build_x0_kernel(const float* __restrict__ a,
                                const float* __restrict__ b,
                                const float* __restrict__ c) {
    int i = blockIdx.x * blockDim.x + threadIdx.x;  // over NN*16 float4
    if (i >= NN * 16) return;
    int v = i >> 4;
    float4 val;
    if (v < NI)            val = ((const float4*)a)[i];
    else if (v < NI + NU)  val = ((const float4*)b)[i - NI * 16];
    else                   val = ((const float4*)c)[i - (NI + NU) * 16];
    ((float4*)g_facc)[i] = val;
}

// ---------------- SGEMM + fused attention dots ----------------
// C[M,NC] = A[M,K] @ B[K,NC]; BM=128, BN=64, BK=16, 256 threads,
// double-buffered smem, FFMA2 inner loop. Epilogue computes
// g_asrc/g_adst[row*AS + head] where head = blockIdx.y (64-col block = 1 head).
template <int K, int NC, int AS>
__global__ void __launch_bounds__(256, 2)
sgemm_att(const float* __restrict__ A, const float* __restrict__ B,
          float* __restrict__ C, int M,
          const float* __restrict__ vs, const float* __restrict__ vd) {
    __shared__ __align__(16) float As[2][16][132];
    __shared__ __align__(16) float Bs[2][16][64];
    const int tid = threadIdx.x;
    const int tr = tid >> 4, tc = tid & 15;
    const int rowBase = blockIdx.x * 128;
    const int colBase = blockIdx.y * 64;
    const int ar0 = tid >> 2;
    const int ar1 = ar0 + 64;
    const int ac  = (tid & 3) * 4;
    const int br  = tid >> 4, bc = (tid & 15) * 4;
    const int NSTEP = K / 16;

    unsigned long long acc[4][4];
    #pragma unroll
    for (int p = 0; p < 4; p++)
        #pragma unroll
        for (int j = 0; j < 4; j++) acc[p][j] = 0ull;

    {
        float4 va0 = make_float4(0.f, 0.f, 0.f, 0.f), va1 = va0;
        if (rowBase + ar0 < M)
            va0 = *(const float4*)&A[(long)(rowBase + ar0) * K + ac];
        if (rowBase + ar1 < M)
            va1 = *(const float4*)&A[(long)(rowBase + ar1) * K + ac];
        As[0][ac + 0][ar0] = va0.x; As[0][ac + 1][ar0] = va0.y;
        As[0][ac + 2][ar0] = va0.z; As[0][ac + 3][ar0] = va0.w;
        As[0][ac + 0][ar1] = va1.x; As[0][ac + 1][ar1] = va1.y;
        As[0][ac + 2][ar1] = va1.z; As[0][ac + 3][ar1] = va1.w;
        float4 vb = *(const float4*)&B[(long)br * NC + colBase + bc];
        *(float4*)&Bs[0][br][bc] = vb;
    }
    __syncthreads();

    for (int s = 0; s < NSTEP; s++) {
        const int cur = s & 1;
        float4 va0, va1, vb;
        const bool pf = (s + 1 < NSTEP);
        if (pf) {
            int k0 = (s + 1) * 16;
            va0 = make_float4(0.f, 0.f, 0.f, 0.f); va1 = va0;
            if (rowBase + ar0 < M)
                va0 = *(const float4*)&A[(long)(rowBase + ar0) * K + k0 + ac];
            if (rowBase + ar1 < M)
                va1 = *(const float4*)&A[(long)(rowBase + ar1) * K + k0 + ac];
            vb = *(const float4*)&B[(long)(k0 + br) * NC + colBase + bc];
        }
        #pragma unroll
        for (int kk = 0; kk < 16; kk++) {
            ulonglong2 av0 = *(const ulonglong2*)&As[cur][kk][tr * 8];
            ulonglong2 av1 = *(const ulonglong2*)&As[cur][kk][tr * 8 + 4];
            float4 bv = *(const float4*)&Bs[cur][kk][tc * 4];
            unsigned long long bb0 = pk2(bv.x, bv.x);
            unsigned long long bb1 = pk2(bv.y, bv.y);
            unsigned long long bb2 = pk2(bv.z, bv.z);
            unsigned long long bb3 = pk2(bv.w, bv.w);
            unsigned long long ap0 = av0.x, ap1 = av0.y, ap2 = av1.x, ap3 = av1.y;
            fma2(acc[0][0], ap0, bb0); fma2(acc[0][1], ap0, bb1);
            fma2(acc[0][2], ap0, bb2); fma2(acc[0][3], ap0, bb3);
            fma2(acc[1][0], ap1, bb0); fma2(acc[1][1], ap1, bb1);
            fma2(acc[1][2], ap1, bb2); fma2(acc[1][3], ap1, bb3);
            fma2(acc[2][0], ap2, bb0); fma2(acc[2][1], ap2, bb1);
            fma2(acc[2][2], ap2, bb2); fma2(acc[2][3], ap2, bb3);
            fma2(acc[3][0], ap3, bb0); fma2(acc[3][1], ap3, bb1);
            fma2(acc[3][2], ap3, bb2); fma2(acc[3][3], ap3, bb3);
        }
        if (pf) {
            const int nb = 1 - cur;
            As[nb][ac + 0][ar0] = va0.x; As[nb][ac + 1][ar0] = va0.y;
            As[nb][ac + 2][ar0] = va0.z; As[nb][ac + 3][ar0] = va0.w;
            As[nb][ac + 0][ar1] = va1.x; As[nb][ac + 1][ar1] = va1.y;
            As[nb][ac + 2][ar1] = va1.z; As[nb][ac + 3][ar1] = va1.w;
            *(float4*)&Bs[nb][br][bc] = vb;
            __syncthreads();
        }
    }

    // unpack: rows tr*8+q (q=0..7), cols colBase + tc*4 + j
    float r[8][4];
    #pragma unroll
    for (int p = 0; p < 4; p++)
        #pragma unroll
        for (int j = 0; j < 4; j++)
            unpk2(acc[p][j], r[2 * p][j], r[2 * p + 1][j]);

    #pragma unroll
    for (int q = 0; q < 8; q++) {
        int row = rowBase + tr * 8 + q;
        if (row < M)
            *(float4*)&C[(long)row * NC + colBase + tc * 4] =
                make_float4(r[q][0], r[q][1], r[q][2], r[q][3]);
    }

    // fused attention dots: reduce over the 64 cols of this head
    float vsv[4], vdv[4];
    #pragma unroll
    for (int j = 0; j < 4; j++) {
        vsv[j] = vs[colBase + tc * 4 + j];
        vdv[j] = vd[colBase + tc * 4 + j];
    }
    const int head = blockIdx.y;
    #pragma unroll
    for (int q = 0; q < 8; q++) {
        float sdot = r[q][0] * vsv[0] + r[q][1] * vsv[1] +
                     r[q][2] * vsv[2] + r[q][3] * vsv[3];
        float ddot = r[q][0] * vdv[0] + r[q][1] * vdv[1] +
                     r[q][2] * vdv[2] + r[q][3] * vdv[3];
        #pragma unroll
        for (int off = 8; off; off >>= 1) {
            sdot += __shfl_xor_sync(0xffffffffu, sdot, off);
            ddot += __shfl_xor_sync(0xffffffffu, ddot, off);
        }
        int row = rowBase + tr * 8 + q;
        if (tc == 0 && row < M) {
            g_asrc[(long)row * AS + head] = sdot;
            g_adst[(long)row * AS + head] = ddot;
        }
    }
}

__device__ __forceinline__ float lrelu(float x) { return x > 0.f ? x : 0.2f * x; }

// ---------------- aggregation, H=2: one warp per (node, head) ----------------
// computes softmax stats (stored to g_dstat for the alpha kernel), aggregates
// features, writes relu output for next layer, facc += 0.5*x.
__global__ void agg_h2_kernel(const float* __restrict__ xw,
                              const float* __restrict__ bias,
                              float* __restrict__ hout) {
    int gw = (blockIdx.x * blockDim.x + threadIdx.x) >> 5;
    if (gw >= 2 * NN) return;
    int v = gw >> 1, h = gw & 1;
    int lane = threadIdx.x & 31;
    int beg = g_offs[v];
    int deg = g_offs[v + 1] - beg;
    float ad = g_adst[2 * v + h];

    // pass 1: online softmax stats
    float m = -3.0e38f, ssum = 0.f;
    for (int i = lane; i < deg; i += 32) {
        int sc = g_srcs[beg + i];
        float e = lrelu(g_asrc[2 * sc + h] + ad);
        float n = fmaxf(m, e);
        ssum = ssum * __expf(m - n) + __expf(e - n);
        m = n;
    }
    #pragma unroll
    for (int o = 16; o; o >>= 1) {
        float om = __shfl_xor_sync(0xffffffffu, m, o);
        float os = __shfl_xor_sync(0xffffffffu, ssum, o);
        float nm = fmaxf(m, om);
        ssum = ssum * __expf(m - nm) + os * __expf(om - nm);
        m = nm;
    }
    float inv = 1.f / (ssum + 1e-16f);
    if (lane == 0)
        g_dstat[2 * v + h] = make_float4(ad, m, inv, 0.f);

    // pass 2: weighted feature gather (lane owns 2 feats of head h)
    unsigned long long acc = 0ull;
    const unsigned long long* xh = (const unsigned long long*)xw;
    const long hoff = h * 32 + lane;
    for (int base = 0; base < deg; base += 32) {
        int i = base + lane;
        float al = 0.f;
        int sidx = 0;
        if (i < deg) {
            sidx = g_srcs[beg + i];
            al = __expf(lrelu(g_asrc[2 * sidx + h] + ad) - m) * inv;
        }
        int cnt = min(32, deg - base);
        int t = 0;
        for (; t + 8 <= cnt; t += 8) {
            int s0 = __shfl_sync(0xffffffffu, sidx, t);
            int s1 = __shfl_sync(0xffffffffu, sidx, t + 1);
            int s2 = __shfl_sync(0xffffffffu, sidx, t + 2);
            int s3 = __shfl_sync(0xffffffffu, sidx, t + 3);
            int s4 = __shfl_sync(0xffffffffu, sidx, t + 4);
            int s5 = __shfl_sync(0xffffffffu, sidx, t + 5);
            int s6 = __shfl_sync(0xffffffffu, sidx, t + 6);
            int s7 = __shfl_sync(0xffffffffu, sidx, t + 7);
            float a0 = __shfl_sync(0xffffffffu, al, t);
            float a1 = __shfl_sync(0xffffffffu, al, t + 1);
            float a2 = __shfl_sync(0xffffffffu, al, t + 2);
            float a3 = __shfl_sync(0xffffffffu, al, t + 3);
            float a4 = __shfl_sync(0xffffffffu, al, t + 4);
            float a5 = __shfl_sync(0xffffffffu, al, t + 5);
            float a6 = __shfl_sync(0xffffffffu, al, t + 6);
            float a7 = __shfl_sync(0xffffffffu, al, t + 7);
            unsigned long long x0 = xh[(long)s0 * 64 + hoff];
            unsigned long long x1 = xh[(long)s1 * 64 + hoff];
            unsigned long long x2 = xh[(long)s2 * 64 + hoff];
            unsigned long long x3 = xh[(long)s3 * 64 + hoff];
            unsigned long long x4 = xh[(long)s4 * 64 + hoff];
            unsigned long long x5 = xh[(long)s5 * 64 + hoff];
            unsigned long long x6 = xh[(long)s6 * 64 + hoff];
            unsigned long long x7 = xh[(long)s7 * 64 + hoff];
            fma2(acc, pk2(a0, a0), x0);
            fma2(acc, pk2(a1, a1), x1);
            fma2(acc, pk2(a2, a2), x2);
            fma2(acc, pk2(a3, a3), x3);
            fma2(acc, pk2(a4, a4), x4);
            fma2(acc, pk2(a5, a5), x5);
            fma2(acc, pk2(a6, a6), x6);
            fma2(acc, pk2(a7, a7), x7);
        }
        for (; t + 4 <= cnt; t += 4) {
            int s0 = __shfl_sync(0xffffffffu, sidx, t);
            int s1 = __shfl_sync(0xffffffffu, sidx, t + 1);
            int s2 = __shfl_sync(0xffffffffu, sidx, t + 2);
            int s3 = __shfl_sync(0xffffffffu, sidx, t + 3);
            float a0 = __shfl_sync(0xffffffffu, al, t);
            float a1 = __shfl_sync(0xffffffffu, al, t + 1);
            float a2 = __shfl_sync(0xffffffffu, al, t + 2);
            float a3 = __shfl_sync(0xffffffffu, al, t + 3);
            unsigned long long x0 = xh[(long)s0 * 64 + hoff];
            unsigned long long x1 = xh[(long)s1 * 64 + hoff];
            unsigned long long x2 = xh[(long)s2 * 64 + hoff];
            unsigned long long x3 = xh[(long)s3 * 64 + hoff];
            fma2(acc, pk2(a0, a0), x0);
            fma2(acc, pk2(a1, a1), x1);
            fma2(acc, pk2(a2, a2), x2);
            fma2(acc, pk2(a3, a3), x3);
        }
        for (; t < cnt; t++) {
            int s0 = __shfl_sync(0xffffffffu, sidx, t);
            float a0 = __shfl_sync(0xffffffffu, al, t);
            unsigned long long x0 = xh[(long)s0 * 64 + hoff];
            fma2(acc, pk2(a0, a0), x0);
        }
    }

    // epilogue
    float xa, xb;
    unpk2(acc, xa, xb);
    int f = h * 64 + lane * 2;
    xa += bias[f];
    xb += bias[f + 1];
    ((float2*)hout)[(long)v * 64 + h * 32 + lane] =
        make_float2(fmaxf(xa, 0.f), fmaxf(xb, 0.f));
    atomicAdd(&g_facc[(long)v * 64 + lane * 2], 0.5f * xa);
    atomicAdd(&g_facc[(long)v * 64 + lane * 2 + 1], 0.5f * xb);
}

// ---------------- aggregation, H=1 (layer 3) + final outputs ----------------
__global__ void agg_h1_kernel(const float* __restrict__ xw,
                              const float* __restrict__ bias,
                              float* __restrict__ out) {
    int v = (blockIdx.x * blockDim.x + threadIdx.x) >> 5;
    if (v >= NN) return;
    int lane = threadIdx.x & 31;
    int beg = g_offs[v];
    int deg = g_offs[v + 1] - beg;
    float ad = g_adst[v];

    float m = -3.0e38f, ssum = 0.f;
    for (int i = lane; i < deg; i += 32) {
        int sc = g_srcs[beg + i];
        float e = lrelu(g_asrc[sc] + ad);
        float n = fmaxf(m, e);
        ssum = ssum * __expf(m - n) + __expf(e - n);
        m = n;
    }
    #pragma unroll
    for (int o = 16; o; o >>= 1) {
        float om = __shfl_xor_sync(0xffffffffu, m, o);
        float os = __shfl_xor_sync(0xffffffffu, ssum, o);
        float nm = fmaxf(m, om);
        ssum = ssum * __expf(m - nm) + os * __expf(om - nm);
        m = nm;
    }
    float inv = 1.f / (ssum + 1e-16f);
    if (lane == 0)
        g_dstat[v] = make_float4(ad, m, inv, 0.f);

    unsigned long long acc = 0ull;
    const unsigned long long* xw1 = (const unsigned long long*)xw;
    for (int base = 0; base < deg; base += 32) {
        int i = base + lane;
        float al = 0.f;
        int sidx = 0;
        if (i < deg) {
            sidx = g_srcs[beg + i];
            al = __expf(lrelu(g_asrc[sidx] + ad) - m) * inv;
        }
        int cnt = min(32, deg - base);
        int t = 0;
        for (; t + 8 <= cnt; t += 8) {
            int s0 = __shfl_sync(0xffffffffu, sidx, t);
            int s1 = __shfl_sync(0xffffffffu, sidx, t + 1);
            int s2 = __shfl_sync(0xffffffffu, sidx, t + 2);
            int s3 = __shfl_sync(0xffffffffu, sidx, t + 3);
            int s4 = __shfl_sync(0xffffffffu, sidx, t + 4);
            int s5 = __shfl_sync(0xffffffffu, sidx, t + 5);
            int s6 = __shfl_sync(0xffffffffu, sidx, t + 6);
            int s7 = __shfl_sync(0xffffffffu, sidx, t + 7);
            float a0 = __shfl_sync(0xffffffffu, al, t);
            float a1 = __shfl_sync(0xffffffffu, al, t + 1);
            float a2 = __shfl_sync(0xffffffffu, al, t + 2);
            float a3 = __shfl_sync(0xffffffffu, al, t + 3);
            float a4 = __shfl_sync(0xffffffffu, al, t + 4);
            float a5 = __shfl_sync(0xffffffffu, al, t + 5);
            float a6 = __shfl_sync(0xffffffffu, al, t + 6);
            float a7 = __shfl_sync(0xffffffffu, al, t + 7);
            unsigned long long x0 = xw1[(long)s0 * 32 + lane];
            unsigned long long x1 = xw1[(long)s1 * 32 + lane];
            unsigned long long x2 = xw1[(long)s2 * 32 + lane];
            unsigned long long x3 = xw1[(long)s3 * 32 + lane];
            unsigned long long x4 = xw1[(long)s4 * 32 + lane];
            unsigned long long x5 = xw1[(long)s5 * 32 + lane];
            unsigned long long x6 = xw1[(long)s6 * 32 + lane];
            unsigned long long x7 = xw1[(long)s7 * 32 + lane];
            fma2(acc, pk2(a0, a0), x0);
            fma2(acc, pk2(a1, a1), x1);
            fma2(acc, pk2(a2, a2), x2);
            fma2(acc, pk2(a3, a3), x3);
            fma2(acc, pk2(a4, a4), x4);
            fma2(acc, pk2(a5, a5), x5);
            fma2(acc, pk2(a6, a6), x6);
            fma2(acc, pk2(a7, a7), x7);
        }
        for (; t + 4 <= cnt; t += 4) {
            int s0 = __shfl_sync(0xffffffffu, sidx, t);
            int s1 = __shfl_sync(0xffffffffu, sidx, t + 1);
            int s2 = __shfl_sync(0xffffffffu, sidx, t + 2);
            int s3 = __shfl_sync(0xffffffffu, sidx, t + 3);
            float a0 = __shfl_sync(0xffffffffu, al, t);
            float a1 = __shfl_sync(0xffffffffu, al, t + 1);
            float a2 = __shfl_sync(0xffffffffu, al, t + 2);
            float a3 = __shfl_sync(0xffffffffu, al, t + 3);
            unsigned long long x0 = xw1[(long)s0 * 32 + lane];
            unsigned long long x1 = xw1[(long)s1 * 32 + lane];
            unsigned long long x2 = xw1[(long)s2 * 32 + lane];
            unsigned long long x3 = xw1[(long)s3 * 32 + lane];
            fma2(acc, pk2(a0, a0), x0);
            fma2(acc, pk2(a1, a1), x1);
            fma2(acc, pk2(a2, a2), x2);
            fma2(acc, pk2(a3, a3), x3);
        }
        for (; t < cnt; t++) {
            int s0 = __shfl_sync(0xffffffffu, sidx, t);
            float a0 = __shfl_sync(0xffffffffu, al, t);
            unsigned long long x0 = xw1[(long)s0 * 32 + lane];
            fma2(acc, pk2(a0, a0), x0);
        }
    }

    float xa, xb;
    unpk2(acc, xa, xb);
    int f = lane * 2;
    xa += bias[f];
    xb += bias[f + 1];
    float fa = (g_facc[(long)v * 64 + f] + xa) * 0.25f;
    float fb = (g_facc[(long)v * 64 + f + 1] + xb) * 0.25f;
    out[FINALO + (long)v * 64 + f] = fa;
    out[FINALO + (long)v * 64 + f + 1] = fb;
    long seg;
    if (v < NI)            seg = ITEMO + (long)v * 64;
    else if (v < NI + NU)  seg = USERO + (long)(v - NI) * 64;
    else                   seg = FETO + (long)(v - NI - NU) * 64;
    out[seg + f] = fa;
    out[seg + f + 1] = fb;
}

// ---------------- edge-order alpha kernels (coalesced writes) ----------------
__global__ void alpha2_kernel(const int* __restrict__ ei,
                              float* __restrict__ aout) {
    int e = blockIdx.x * blockDim.x + threadIdx.x;
    if (e >= TOTE) return;
    int s, d;
    if (e < NE) {
        s = ei[e];
        d = ei[NE + e];
    } else {
        s = e - NE;
        d = e - NE;
    }
    float2 as = ((const float2*)g_asrc)[s];
    float4 d0 = g_dstat[2 * d];
    float4 d1 = g_dstat[2 * d + 1];
    float a0 = __expf(lrelu(as.x + d0.x) - d0.y) * d0.z;
    float a1 = __expf(lrelu(as.y + d1.x) - d1.y) * d1.z;
    ((float2*)aout)[e] = make_float2(a0, a1);
}

__global__ void alpha1_kernel(const int* __restrict__ ei,
                              float* __restrict__ aout) {
    int e = blockIdx.x * blockDim.x + threadIdx.x;
    if (e >= TOTE) return;
    int s, d;
    if (e < NE) {
        s = ei[e];
        d = ei[NE + e];
    } else {
        s = e - NE;
        d = e - NE;
    }
    float as = g_asrc[s];
    float4 d0 = g_dstat[d];
    aout[e] = __expf(lrelu(as + d0.x) - d0.y) * d0.z;
}

// ---------------- host launch ----------------
extern "C" void kernel_launch(void* const* d_in, const int* in_sizes, int n_in,
                              void* d_out, int out_size) {
    const int*   ei       = (const int*)d_in[0];
    const float* emb_item = (const float*)d_in[1];
    const float* emb_user = (const float*)d_in[2];
    const float* emb_fet  = (const float*)d_in[3];
    const float* W1  = (const float*)d_in[4];
    const float* as1 = (const float*)d_in[5];
    const float* ad1 = (const float*)d_in[6];
    const float* b1  = (const float*)d_in[7];
    const float* W2  = (const float*)d_in[8];
    const float* as2 = (const float*)d_in[9];
    const float* ad2 = (const float*)d_in[10];
    const float* b2  = (const float*)d_in[11];
    const float* W3  = (const float*)d_in[12];
    const float* as3 = (const float*)d_in[13];
    const float* ad3 = (const float*)d_in[14];
    const float* b3  = (const float*)d_in[15];
    float* out = (float*)d_out;

    float *xwp, *hp, *faccp;
    cudaGetSymbolAddress((void**)&xwp, g_xw);
    cudaGetSymbolAddress((void**)&hp, g_h);
    cudaGetSymbolAddress((void**)&faccp, g_facc);

    const int T = 256;
    int nodeBlocks = (NN + T - 1) / T;
    int edgeBlocks = (TOTE + T - 1) / T;
    int warpBlocks = (NN * 32 + T - 1) / T;       // one warp per node
    int warp2Blocks = (2 * NN * 32 + T - 1) / T;  // one warp per (node, head)

    // CSR build
    zero_count_kernel<<<nodeBlocks, T>>>();
    hist_kernel<<<edgeBlocks, T>>>(ei);
    scan_part_kernel<<<SCAN_NB, 256>>>();
    scan_top_kernel<<<1, 512>>>();
    scan_fix_kernel<<<SCAN_NB, 256>>>();
    scatter_kernel<<<edgeBlocks, T>>>(ei);

    // facc = x0
    build_x0_kernel<<<(NN * 16 + T - 1) / T, T>>>(emb_item, emb_user, emb_fet);

    // layer 1
    {
        dim3 g((NN + 127) / 128, 2);
        sgemm_att<64, 128, 2><<<g, T>>>(faccp, W1, xwp, NN, as1, ad1);
    }
    agg_h2_kernel<<<warp2Blocks, T>>>(xwp, b1, hp);
    alpha2_kernel<<<edgeBlocks, T>>>(ei, out + A1OFF);

    // layer 2
    {
        dim3 g((NN + 127) / 128, 2);
        sgemm_att<128, 128, 2><<<g, T>>>(hp, W2, xwp, NN, as2, ad2);
    }
    agg_h2_kernel<<<warp2Blocks, T>>>(xwp, b2, hp);
    alpha2_kernel<<<edgeBlocks, T>>>(ei, out + A2OFF);

    // layer 3
    {
        dim3 g((NN + 127) / 128, 1);
        sgemm_att<128, 64, 1><<<g, T>>>(hp, W3, xwp, NN, as3, ad3);
    }
    agg_h1_kernel<<<warpBlocks, T>>>(xwp, b3, out);
    alpha1_kernel<<<edgeBlocks, T>>>(ei, out + A3OFF);
}

// round 6
// speedup vs baseline: 1.4863x; 1.0592x over previous
#include <cuda_runtime.h>
#include <cuda_bf16.h>

// ---------------- problem constants ----------------
#define NE    1200000   // raw edges
#define NN    100000    // nodes
#define TOTE  1300000   // edges + self loops
#define NI    40000
#define NU    30000
#define NF    30000

// d_out layout (float32), in reference return order
#define ITEMO  0
#define USERO  2560000
#define FETO   4480000
#define FINALO 6400000
#define A1OFF  12800000
#define A2OFF  15400000
#define A3OFF  18000000

#define SCAN_NB 392   // 392*256 = 100352 >= NN

// ---------------- device scratch (no allocations allowed) ----------------
__device__ __align__(16) float g_xw[NN * 128];
__device__ __align__(16) float g_h[NN * 128];
__device__ __align__(16) float g_facc[NN * 64];
__device__ __align__(8)  float g_asrc[NN * 2];
__device__ __align__(8)  float g_adst[NN * 2];
__device__ __align__(16) float4 g_dstat[NN * 2];   // (a_dst, m, inv, _) per (node, head)
__device__ int   g_count[NN];
__device__ int   g_offs[NN + 1];
__device__ int   g_cursor[NN];
__device__ int   g_srcs[TOTE];
__device__ int   g_part[SCAN_NB];
__device__ int   g_partx[SCAN_NB];

// ---------------- f32x2 packed helpers (SASS FFMA2 path) ----------------
__device__ __forceinline__ unsigned long long pk2(float x, float y) {
    unsigned long long r;
    asm("mov.b64 %0, {%1, %2};" : "=l"(r)
        : "r"(__float_as_uint(x)), "r"(__float_as_uint(y)));
    return r;
}
__device__ __forceinline__ void fma2(unsigned long long& d,
                                     unsigned long long a,
                                     unsigned long long b) {
    asm("fma.rn.f32x2 %0, %1, %2, %0;" : "+l"(d) : "l"(a), "l"(b));
}
__device__ __forceinline__ void unpk2(unsigned long long v, float& lo, float& hi) {
    unsigned a, b;
    asm("mov.b64 {%0, %1}, %2;" : "=r"(a), "=r"(b) : "l"(v));
    lo = __uint_as_float(a);
    hi = __uint_as_float(b);
}

__device__ __forceinline__ float lrelu(float x) { return x > 0.f ? x : 0.2f * x; }

// ---------------- CSR build ----------------
__global__ void hist_kernel(const int* __restrict__ ei) {
    int e = blockIdx.x * blockDim.x + threadIdx.x;
    if (e >= TOTE) return;
    int d = (e < NE) ? ei[NE + e] : (e - NE);
    atomicAdd(&g_count[d], 1);
}

__global__ void scan_part_kernel() {
    __shared__ int sh[256];
    int t = threadIdx.x;
    int i = blockIdx.x * 256 + t;
    int c = (i < NN) ? g_count[i] : 0;
    sh[t] = c;
    __syncthreads();
    #pragma unroll
    for (int off = 128; off; off >>= 1) {
        if (t < off) sh[t] += sh[t + off];
        __syncthreads();
    }
    if (t == 0) g_part[blockIdx.x] = sh[0];
}

__global__ void scan_top_kernel() {
    __shared__ int sh[512];
    int t = threadIdx.x;
    int v = (t < SCAN_NB) ? g_part[t] : 0;
    sh[t] = v;
    __syncthreads();
    for (int off = 1; off < 512; off <<= 1) {
        int u = (t >= off) ? sh[t - off] : 0;
        __syncthreads();
        sh[t] += u;
        __syncthreads();
    }
    if (t < SCAN_NB) g_partx[t] = sh[t] - v;
}

__global__ void scan_fix_kernel() {
    __shared__ int sh[256];
    int t = threadIdx.x;
    int i = blockIdx.x * 256 + t;
    int c = (i < NN) ? g_count[i] : 0;
    sh[t] = c;
    __syncthreads();
    for (int off = 1; off < 256; off <<= 1) {
        int u = (t >= off) ? sh[t - off] : 0;
        __syncthreads();
        sh[t] += u;
        __syncthreads();
    }
    int base = g_partx[blockIdx.x];
    int ex = base + sh[t] - c;
    if (i < NN) {
        g_offs[i] = ex;
        g_cursor[i] = ex;
    }
    if (i == NN - 1) g_offs[NN] = base + sh[t];
}

__global__ void scatter_kernel(const int* __restrict__ ei) {
    int e = blockIdx.x * blockDim.x + threadIdx.x;
    if (e >= TOTE) return;
    int d, s;
    if (e < NE) {
        s = ei[e];
        d = ei[NE + e];
    } else {
        s = e - NE;
        d = e - NE;
    }
    int pos = atomicAdd(&g_cursor[d], 1);
    g_srcs[pos] = s;
}

// ---------------- facc = x0 = concat(item,user,fet); also zero g_count -------
__global__ void build_x0_kernel(const float* __restrict__ a,
                                const float* __restrict__ b,
                                const float* __restrict__ c) {
    int i = blockIdx.x * blockDim.x + threadIdx.x;  // over NN*16 float4
    if (i >= NN * 16) return;
    if (i < NN) g_count[i] = 0;
    int v = i >> 4;
    float4 val;
    if (v < NI)            val = ((const float4*)a)[i];
    else if (v < NI + NU)  val = ((const float4*)b)[i - NI * 16];
    else                   val = ((const float4*)c)[i - (NI + NU) * 16];
    ((float4*)g_facc)[i] = val;
}

// ---------------- SGEMM + fused attention dots ----------------
// C[M,NC] = A[M,K] @ B[K,NC]; BM=128, BN=64, BK=16, 256 threads,
// double-buffered smem, FFMA2 inner loop. Epilogue computes
// g_asrc/g_adst[row*AS + head] where head = blockIdx.y.
template <int K, int NC, int AS>
__global__ void __launch_bounds__(256, 2)
sgemm_att(const float* __restrict__ A, const float* __restrict__ B,
          float* __restrict__ C, int M,
          const float* __restrict__ vs, const float* __restrict__ vd) {
    __shared__ __align__(16) float As[2][16][132];
    __shared__ __align__(16) float Bs[2][16][64];
    const int tid = threadIdx.x;
    const int tr = tid >> 4, tc = tid & 15;
    const int rowBase = blockIdx.x * 128;
    const int colBase = blockIdx.y * 64;
    const int ar0 = tid >> 2;
    const int ar1 = ar0 + 64;
    const int ac  = (tid & 3) * 4;
    const int br  = tid >> 4, bc = (tid & 15) * 4;
    const int NSTEP = K / 16;

    unsigned long long acc[4][4];
    #pragma unroll
    for (int p = 0; p < 4; p++)
        #pragma unroll
        for (int j = 0; j < 4; j++) acc[p][j] = 0ull;

    {
        float4 va0 = make_float4(0.f, 0.f, 0.f, 0.f), va1 = va0;
        if (rowBase + ar0 < M)
            va0 = *(const float4*)&A[(long)(rowBase + ar0) * K + ac];
        if (rowBase + ar1 < M)
            va1 = *(const float4*)&A[(long)(rowBase + ar1) * K + ac];
        As[0][ac + 0][ar0] = va0.x; As[0][ac + 1][ar0] = va0.y;
        As[0][ac + 2][ar0] = va0.z; As[0][ac + 3][ar0] = va0.w;
        As[0][ac + 0][ar1] = va1.x; As[0][ac + 1][ar1] = va1.y;
        As[0][ac + 2][ar1] = va1.z; As[0][ac + 3][ar1] = va1.w;
        float4 vb = *(const float4*)&B[(long)br * NC + colBase + bc];
        *(float4*)&Bs[0][br][bc] = vb;
    }
    __syncthreads();

    for (int s = 0; s < NSTEP; s++) {
        const int cur = s & 1;
        float4 va0, va1, vb;
        const bool pf = (s + 1 < NSTEP);
        if (pf) {
            int k0 = (s + 1) * 16;
            va0 = make_float4(0.f, 0.f, 0.f, 0.f); va1 = va0;
            if (rowBase + ar0 < M)
                va0 = *(const float4*)&A[(long)(rowBase + ar0) * K + k0 + ac];
            if (rowBase + ar1 < M)
                va1 = *(const float4*)&A[(long)(rowBase + ar1) * K + k0 + ac];
            vb = *(const float4*)&B[(long)(k0 + br) * NC + colBase + bc];
        }
        #pragma unroll
        for (int kk = 0; kk < 16; kk++) {
            ulonglong2 av0 = *(const ulonglong2*)&As[cur][kk][tr * 8];
            ulonglong2 av1 = *(const ulonglong2*)&As[cur][kk][tr * 8 + 4];
            float4 bv = *(const float4*)&Bs[cur][kk][tc * 4];
            unsigned long long bb0 = pk2(bv.x, bv.x);
            unsigned long long bb1 = pk2(bv.y, bv.y);
            unsigned long long bb2 = pk2(bv.z, bv.z);
            unsigned long long bb3 = pk2(bv.w, bv.w);
            unsigned long long ap0 = av0.x, ap1 = av0.y, ap2 = av1.x, ap3 = av1.y;
            fma2(acc[0][0], ap0, bb0); fma2(acc[0][1], ap0, bb1);
            fma2(acc[0][2], ap0, bb2); fma2(acc[0][3], ap0, bb3);
            fma2(acc[1][0], ap1, bb0); fma2(acc[1][1], ap1, bb1);
            fma2(acc[1][2], ap1, bb2); fma2(acc[1][3], ap1, bb3);
            fma2(acc[2][0], ap2, bb0); fma2(acc[2][1], ap2, bb1);
            fma2(acc[2][2], ap2, bb2); fma2(acc[2][3], ap2, bb3);
            fma2(acc[3][0], ap3, bb0); fma2(acc[3][1], ap3, bb1);
            fma2(acc[3][2], ap3, bb2); fma2(acc[3][3], ap3, bb3);
        }
        if (pf) {
            const int nb = 1 - cur;
            As[nb][ac + 0][ar0] = va0.x; As[nb][ac + 1][ar0] = va0.y;
            As[nb][ac + 2][ar0] = va0.z; As[nb][ac + 3][ar0] = va0.w;
            As[nb][ac + 0][ar1] = va1.x; As[nb][ac + 1][ar1] = va1.y;
            As[nb][ac + 2][ar1] = va1.z; As[nb][ac + 3][ar1] = va1.w;
            *(float4*)&Bs[nb][br][bc] = vb;
            __syncthreads();
        }
    }

    float r[8][4];
    #pragma unroll
    for (int p = 0; p < 4; p++)
        #pragma unroll
        for (int j = 0; j < 4; j++)
            unpk2(acc[p][j], r[2 * p][j], r[2 * p + 1][j]);

    #pragma unroll
    for (int q = 0; q < 8; q++) {
        int row = rowBase + tr * 8 + q;
        if (row < M)
            *(float4*)&C[(long)row * NC + colBase + tc * 4] =
                make_float4(r[q][0], r[q][1], r[q][2], r[q][3]);
    }

    // fused attention dots: reduce over the 64 cols of this head
    float vsv[4], vdv[4];
    #pragma unroll
    for (int j = 0; j < 4; j++) {
        vsv[j] = vs[colBase + tc * 4 + j];
        vdv[j] = vd[colBase + tc * 4 + j];
    }
    const int head = blockIdx.y;
    #pragma unroll
    for (int q = 0; q < 8; q++) {
        float sdot = r[q][0] * vsv[0] + r[q][1] * vsv[1] +
                     r[q][2] * vsv[2] + r[q][3] * vsv[3];
        float ddot = r[q][0] * vdv[0] + r[q][1] * vdv[1] +
                     r[q][2] * vdv[2] + r[q][3] * vdv[3];
        #pragma unroll
        for (int off = 8; off; off >>= 1) {
            sdot += __shfl_xor_sync(0xffffffffu, sdot, off);
            ddot += __shfl_xor_sync(0xffffffffu, ddot, off);
        }
        int row = rowBase + tr * 8 + q;
        if (tc == 0 && row < M) {
            g_asrc[(long)row * AS + head] = sdot;
            g_adst[(long)row * AS + head] = ddot;
        }
    }
}

// ---------------- aggregation, H=2: one warp per (node, head) ----------------
__global__ void agg_h2_kernel(const float* __restrict__ xw,
                              const float* __restrict__ bias,
                              float* __restrict__ hout) {
    int gw = (blockIdx.x * blockDim.x + threadIdx.x) >> 5;
    if (gw >= 2 * NN) return;
    int v = gw >> 1, h = gw & 1;
    int lane = threadIdx.x & 31;
    int beg = g_offs[v];
    int deg = g_offs[v + 1] - beg;
    float ad = g_adst[2 * v + h];

    unsigned long long acc = 0ull;
    const unsigned long long* xh = (const unsigned long long*)xw;
    const long hoff = h * 32 + lane;

    if (deg <= 32) {
        // ---- fast path: edges fully register-resident ----
        int sidx = 0;
        float e = -3.0e38f;
        if (lane < deg) {
            sidx = g_srcs[beg + lane];
            e = lrelu(g_asrc[2 * sidx + h] + ad);
        }
        float m = e;
        #pragma unroll
        for (int o = 16; o; o >>= 1)
            m = fmaxf(m, __shfl_xor_sync(0xffffffffu, m, o));
        float p = (lane < deg) ? __expf(e - m) : 0.f;
        float ssum = p;
        #pragma unroll
        for (int o = 16; o; o >>= 1)
            ssum += __shfl_xor_sync(0xffffffffu, ssum, o);
        float inv = 1.f / (ssum + 1e-16f);
        if (lane == 0)
            g_dstat[2 * v + h] = make_float4(ad, m, inv, 0.f);
        float al = p * inv;

        int t = 0;
        for (; t + 8 <= deg; t += 8) {
            int s0 = __shfl_sync(0xffffffffu, sidx, t);
            int s1 = __shfl_sync(0xffffffffu, sidx, t + 1);
            int s2 = __shfl_sync(0xffffffffu, sidx, t + 2);
            int s3 = __shfl_sync(0xffffffffu, sidx, t + 3);
            int s4 = __shfl_sync(0xffffffffu, sidx, t + 4);
            int s5 = __shfl_sync(0xffffffffu, sidx, t + 5);
            int s6 = __shfl_sync(0xffffffffu, sidx, t + 6);
            int s7 = __shfl_sync(0xffffffffu, sidx, t + 7);
            float a0 = __shfl_sync(0xffffffffu, al, t);
            float a1 = __shfl_sync(0xffffffffu, al, t + 1);
            float a2 = __shfl_sync(0xffffffffu, al, t + 2);
            float a3 = __shfl_sync(0xffffffffu, al, t + 3);
            float a4 = __shfl_sync(0xffffffffu, al, t + 4);
            float a5 = __shfl_sync(0xffffffffu, al, t + 5);
            float a6 = __shfl_sync(0xffffffffu, al, t + 6);
            float a7 = __shfl_sync(0xffffffffu, al, t + 7);
            unsigned long long x0 = xh[(long)s0 * 64 + hoff];
            unsigned long long x1 = xh[(long)s1 * 64 + hoff];
            unsigned long long x2 = xh[(long)s2 * 64 + hoff];
            unsigned long long x3 = xh[(long)s3 * 64 + hoff];
            unsigned long long x4 = xh[(long)s4 * 64 + hoff];
            unsigned long long x5 = xh[(long)s5 * 64 + hoff];
            unsigned long long x6 = xh[(long)s6 * 64 + hoff];
            unsigned long long x7 = xh[(long)s7 * 64 + hoff];
            fma2(acc, pk2(a0, a0), x0);
            fma2(acc, pk2(a1, a1), x1);
            fma2(acc, pk2(a2, a2), x2);
            fma2(acc, pk2(a3, a3), x3);
            fma2(acc, pk2(a4, a4), x4);
            fma2(acc, pk2(a5, a5), x5);
            fma2(acc, pk2(a6, a6), x6);
            fma2(acc, pk2(a7, a7), x7);
        }
        for (; t < deg; t++) {
            int s0 = __shfl_sync(0xffffffffu, sidx, t);
            float a0 = __shfl_sync(0xffffffffu, al, t);
            unsigned long long x0 = xh[(long)s0 * 64 + hoff];
            fma2(acc, pk2(a0, a0), x0);
        }
    } else {
        // ---- slow path (deg > 32): two passes ----
        float m = -3.0e38f, ssum = 0.f;
        for (int i = lane; i < deg; i += 32) {
            int sc = g_srcs[beg + i];
            float e = lrelu(g_asrc[2 * sc + h] + ad);
            float n = fmaxf(m, e);
            ssum = ssum * __expf(m - n) + __expf(e - n);
            m = n;
        }
        #pragma unroll
        for (int o = 16; o; o >>= 1) {
            float om = __shfl_xor_sync(0xffffffffu, m, o);
            float os = __shfl_xor_sync(0xffffffffu, ssum, o);
            float nm = fmaxf(m, om);
            ssum = ssum * __expf(m - nm) + os * __expf(om - nm);
            m = nm;
        }
        float inv = 1.f / (ssum + 1e-16f);
        if (lane == 0)
            g_dstat[2 * v + h] = make_float4(ad, m, inv, 0.f);

        for (int base = 0; base < deg; base += 32) {
            int i = base + lane;
            float al = 0.f;
            int sidx = 0;
            if (i < deg) {
                sidx = g_srcs[beg + i];
                al = __expf(lrelu(g_asrc[2 * sidx + h] + ad) - m) * inv;
            }
            int cnt = min(32, deg - base);
            for (int t = 0; t < cnt; t++) {
                int s0 = __shfl_sync(0xffffffffu, sidx, t);
                float a0 = __shfl_sync(0xffffffffu, al, t);
                unsigned long long x0 = xh[(long)s0 * 64 + hoff];
                fma2(acc, pk2(a0, a0), x0);
            }
        }
    }

    // epilogue
    float xa, xb;
    unpk2(acc, xa, xb);
    int f = h * 64 + lane * 2;
    xa += bias[f];
    xb += bias[f + 1];
    ((float2*)hout)[(long)v * 64 + h * 32 + lane] =
        make_float2(fmaxf(xa, 0.f), fmaxf(xb, 0.f));
    atomicAdd(&g_facc[(long)v * 64 + lane * 2], 0.5f * xa);
    atomicAdd(&g_facc[(long)v * 64 + lane * 2 + 1], 0.5f * xb);
}

// ---------------- aggregation, H=1 (layer 3) + final outputs ----------------
__global__ void agg_h1_kernel(const float* __restrict__ xw,
                              const float* __restrict__ bias,
                              float* __restrict__ out) {
    int v = (blockIdx.x * blockDim.x + threadIdx.x) >> 5;
    if (v >= NN) return;
    int lane = threadIdx.x & 31;
    int beg = g_offs[v];
    int deg = g_offs[v + 1] - beg;
    float ad = g_adst[v];

    unsigned long long acc = 0ull;
    const unsigned long long* xw1 = (const unsigned long long*)xw;

    if (deg <= 32) {
        int sidx = 0;
        float e = -3.0e38f;
        if (lane < deg) {
            sidx = g_srcs[beg + lane];
            e = lrelu(g_asrc[sidx] + ad);
        }
        float m = e;
        #pragma unroll
        for (int o = 16; o; o >>= 1)
            m = fmaxf(m, __shfl_xor_sync(0xffffffffu, m, o));
        float p = (lane < deg) ? __expf(e - m) : 0.f;
        float ssum = p;
        #pragma unroll
        for (int o = 16; o; o >>= 1)
            ssum += __shfl_xor_sync(0xffffffffu, ssum, o);
        float inv = 1.f / (ssum + 1e-16f);
        if (lane == 0)
            g_dstat[v] = make_float4(ad, m, inv, 0.f);
        float al = p * inv;

        int t = 0;
        for (; t + 8 <= deg; t += 8) {
            int s0 = __shfl_sync(0xffffffffu, sidx, t);
            int s1 = __shfl_sync(0xffffffffu, sidx, t + 1);
            int s2 = __shfl_sync(0xffffffffu, sidx, t + 2);
            int s3 = __shfl_sync(0xffffffffu, sidx, t + 3);
            int s4 = __shfl_sync(0xffffffffu, sidx, t + 4);
            int s5 = __shfl_sync(0xffffffffu, sidx, t + 5);
            int s6 = __shfl_sync(0xffffffffu, sidx, t + 6);
            int s7 = __shfl_sync(0xffffffffu, sidx, t + 7);
            float a0 = __shfl_sync(0xffffffffu, al, t);
            float a1 = __shfl_sync(0xffffffffu, al, t + 1);
            float a2 = __shfl_sync(0xffffffffu, al, t + 2);
            float a3 = __shfl_sync(0xffffffffu, al, t + 3);
            float a4 = __shfl_sync(0xffffffffu, al, t + 4);
            float a5 = __shfl_sync(0xffffffffu, al, t + 5);
            float a6 = __shfl_sync(0xffffffffu, al, t + 6);
            float a7 = __shfl_sync(0xffffffffu, al, t + 7);
            unsigned long long x0 = xw1[(long)s0 * 32 + lane];
            unsigned long long x1 = xw1[(long)s1 * 32 + lane];
            unsigned long long x2 = xw1[(long)s2 * 32 + lane];
            unsigned long long x3 = xw1[(long)s3 * 32 + lane];
            unsigned long long x4 = xw1[(long)s4 * 32 + lane];
            unsigned long long x5 = xw1[(long)s5 * 32 + lane];
            unsigned long long x6 = xw1[(long)s6 * 32 + lane];
            unsigned long long x7 = xw1[(long)s7 * 32 + lane];
            fma2(acc, pk2(a0, a0), x0);
            fma2(acc, pk2(a1, a1), x1);
            fma2(acc, pk2(a2, a2), x2);
            fma2(acc, pk2(a3, a3), x3);
            fma2(acc, pk2(a4, a4), x4);
            fma2(acc, pk2(a5, a5), x5);
            fma2(acc, pk2(a6, a6), x6);
            fma2(acc, pk2(a7, a7), x7);
        }
        for (; t < deg; t++) {
            int s0 = __shfl_sync(0xffffffffu, sidx, t);
            float a0 = __shfl_sync(0xffffffffu, al, t);
            unsigned long long x0 = xw1[(long)s0 * 32 + lane];
            fma2(acc, pk2(a0, a0), x0);
        }
    } else {
        float m = -3.0e38f, ssum = 0.f;
        for (int i = lane; i < deg; i += 32) {
            int sc = g_srcs[beg + i];
            float e = lrelu(g_asrc[sc] + ad);
            float n = fmaxf(m, e);
            ssum = ssum * __expf(m - n) + __expf(e - n);
            m = n;
        }
        #pragma unroll
        for (int o = 16; o; o >>= 1) {
            float om = __shfl_xor_sync(0xffffffffu, m, o);
            float os = __shfl_xor_sync(0xffffffffu, ssum, o);
            float nm = fmaxf(m, om);
            ssum = ssum * __expf(m - nm) + os * __expf(om - nm);
            m = nm;
        }
        float inv = 1.f / (ssum + 1e-16f);
        if (lane == 0)
            g_dstat[v] = make_float4(ad, m, inv, 0.f);

        for (int base = 0; base < deg; base += 32) {
            int i = base + lane;
            float al = 0.f;
            int sidx = 0;
            if (i < deg) {
                sidx = g_srcs[beg + i];
                al = __expf(lrelu(g_asrc[sidx] + ad) - m) * inv;
            }
            int cnt = min(32, deg - base);
            for (int t = 0; t < cnt; t++) {
                int s0 = __shfl_sync(0xffffffffu, sidx, t);
                float a0 = __shfl_sync(0xffffffffu, al, t);
                unsigned long long x0 = xw1[(long)s0 * 32 + lane];
                fma2(acc, pk2(a0, a0), x0);
            }
        }
    }

    float xa, xb;
    unpk2(acc, xa, xb);
    int f = lane * 2;
    xa += bias[f];
    xb += bias[f + 1];
    float fa = (g_facc[(long)v * 64 + f] + xa) * 0.25f;
    float fb = (g_facc[(long)v * 64 + f + 1] + xb) * 0.25f;
    out[FINALO + (long)v * 64 + f] = fa;
    out[FINALO + (long)v * 64 + f + 1] = fb;
    long seg;
    if (v < NI)            seg = ITEMO + (long)v * 64;
    else if (v < NI + NU)  seg = USERO + (long)(v - NI) * 64;
    else                   seg = FETO + (long)(v - NI - NU) * 64;
    out[seg + f] = fa;
    out[seg + f + 1] = fb;
}

// ---------------- edge-order alpha kernels (coalesced writes) ----------------
__global__ void alpha2_kernel(const int* __restrict__ ei,
                              float* __restrict__ aout) {
    int e = blockIdx.x * blockDim.x + threadIdx.x;
    if (e >= TOTE) return;
    int s, d;
    if (e < NE) {
        s = ei[e];
        d = ei[NE + e];
    } else {
        s = e - NE;
        d = e - NE;
    }
    float2 as = ((const float2*)g_asrc)[s];
    float4 d0 = g_dstat[2 * d];
    float4 d1 = g_dstat[2 * d + 1];
    float a0 = __expf(lrelu(as.x + d0.x) - d0.y) * d0.z;
    float a1 = __expf(lrelu(as.y + d1.x) - d1.y) * d1.z;
    ((float2*)aout)[e] = make_float2(a0, a1);
}

__global__ void alpha1_kernel(const int* __restrict__ ei,
                              float* __restrict__ aout) {
    int e = blockIdx.x * blockDim.x + threadIdx.x;
    if (e >= TOTE) return;
    int s, d;
    if (e < NE) {
        s = ei[e];
        d = ei[NE + e];
    } else {
        s = e - NE;
        d = e - NE;
    }
    float as = g_asrc[s];
    float4 d0 = g_dstat[d];
    aout[e] = __expf(lrelu(as + d0.x) - d0.y) * d0.z;
}

// ---------------- host launch ----------------
extern "C" void kernel_launch(void* const* d_in, const int* in_sizes, int n_in,
                              void* d_out, int out_size) {
    const int*   ei       = (const int*)d_in[0];
    const float* emb_item = (const float*)d_in[1];
    const float* emb_user = (const float*)d_in[2];
    const float* emb_fet  = (const float*)d_in[3];
    const float* W1  = (const float*)d_in[4];
    const float* as1 = (const float*)d_in[5];
    const float* ad1 = (const float*)d_in[6];
    const float* b1  = (const float*)d_in[7];
    const float* W2  = (const float*)d_in[8];
    const float* as2 = (const float*)d_in[9];
    const float* ad2 = (const float*)d_in[10];
    const float* b2  = (const float*)d_in[11];
    const float* W3  = (const float*)d_in[12];
    const float* as3 = (const float*)d_in[13];
    const float* ad3 = (const float*)d_in[14];
    const float* b3  = (const float*)d_in[15];
    float* out = (float*)d_out;

    float *xwp, *hp, *faccp;
    cudaGetSymbolAddress((void**)&xwp, g_xw);
    cudaGetSymbolAddress((void**)&hp, g_h);
    cudaGetSymbolAddress((void**)&faccp, g_facc);

    const int T = 256;
    int edgeBlocks = (TOTE + T - 1) / T;
    int warpBlocks = (NN * 32 + T - 1) / T;       // one warp per node
    int warp2Blocks = (2 * NN * 32 + T - 1) / T;  // one warp per (node, head)

    // idx 0: x0 concat + facc init + count zero
    build_x0_kernel<<<(NN * 16 + T - 1) / T, T>>>(emb_item, emb_user, emb_fet);
    // idx 1-2
    hist_kernel<<<edgeBlocks, T>>>(ei);
    scan_part_kernel<<<SCAN_NB, 256>>>();
    // idx 3: layer-1 GEMM (profiled by ncu) — only depends on x0
    {
        dim3 g((NN + 127) / 128, 2);
        sgemm_att<64, 128, 2><<<g, T>>>(faccp, W1, xwp, NN, as1, ad1);
    }
    // idx 4-6: finish CSR
    scan_top_kernel<<<1, 512>>>();
    scan_fix_kernel<<<SCAN_NB, 256>>>();
    scatter_kernel<<<edgeBlocks, T>>>(ei);

    // layer 1 aggregation
    agg_h2_kernel<<<warp2Blocks, T>>>(xwp, b1, hp);
    alpha2_kernel<<<edgeBlocks, T>>>(ei, out + A1OFF);

    // layer 2
    {
        dim3 g((NN + 127) / 128, 2);
        sgemm_att<128, 128, 2><<<g, T>>>(hp, W2, xwp, NN, as2, ad2);
    }
    agg_h2_kernel<<<warp2Blocks, T>>>(xwp, b2, hp);
    alpha2_kernel<<<edgeBlocks, T>>>(ei, out + A2OFF);

    // layer 3
    {
        dim3 g((NN + 127) / 128, 1);
        sgemm_att<128, 64, 1><<<g, T>>>(hp, W3, xwp, NN, as3, ad3);
    }
    agg_h1_kernel<<<warpBlocks, T>>>(xwp, b3, out);
    alpha1_kernel<<<edgeBlocks, T>>>(ei, out + A3OFF);
}

// round 7
// speedup vs baseline: 1.6783x; 1.1292x over previous
#include <cuda_runtime.h>
#include <cuda_bf16.h>
#include <cstdint>

// ---------------- problem constants ----------------
#define NE    1200000   // raw edges
#define NN    100000    // nodes
#define TOTE  1300000   // edges + self loops
#define NI    40000
#define NU    30000
#define NF    30000

// d_out layout (float32), in reference return order
#define ITEMO  0
#define USERO  2560000
#define FETO   4480000
#define FINALO 6400000
#define A1OFF  12800000
#define A2OFF  15400000
#define A3OFF  18000000

#define SCAN_NB 392   // 392*256 = 100352 >= NN

// ---------------- device scratch (no allocations allowed) ----------------
__device__ __align__(16) float g_xw[NN * 128];
__device__ __align__(16) float g_facc[NN * 64];
__device__ __align__(8)  float g_asrc[NN * 2];
__device__ __align__(8)  float g_adst[NN * 2];
__device__ __align__(16) float4 g_dstat[NN * 2];   // (a_dst, m, inv, _) per (node, head)
__device__ int   g_count[NN];
__device__ int   g_offs[NN + 1];
__device__ int   g_cursor[NN];
__device__ int   g_srcs[TOTE];
__device__ int   g_part[SCAN_NB];
__device__ int   g_partx[SCAN_NB];
// bf16 split operands for tensor-core GEMMs
__device__ __align__(16) __nv_bfloat16 g_x0h[NN * 64];
__device__ __align__(16) __nv_bfloat16 g_x0l[NN * 64];
__device__ __align__(16) __nv_bfloat16 g_hh[NN * 128];
__device__ __align__(16) __nv_bfloat16 g_hl[NN * 128];
__device__ __align__(16) __nv_bfloat16 g_w1h[64 * 128];
__device__ __align__(16) __nv_bfloat16 g_w1l[64 * 128];
__device__ __align__(16) __nv_bfloat16 g_w2h[128 * 128];
__device__ __align__(16) __nv_bfloat16 g_w2l[128 * 128];
__device__ __align__(16) __nv_bfloat16 g_w3h[128 * 64];
__device__ __align__(16) __nv_bfloat16 g_w3l[128 * 64];

// ---------------- f32x2 packed helpers (SASS FFMA2 path, agg kernels) -------
__device__ __forceinline__ unsigned long long pk2(float x, float y) {
    unsigned long long r;
    asm("mov.b64 %0, {%1, %2};" : "=l"(r)
        : "r"(__float_as_uint(x)), "r"(__float_as_uint(y)));
    return r;
}
__device__ __forceinline__ void fma2(unsigned long long& d,
                                     unsigned long long a,
                                     unsigned long long b) {
    asm("fma.rn.f32x2 %0, %1, %2, %0;" : "+l"(d) : "l"(a), "l"(b));
}
__device__ __forceinline__ void unpk2(unsigned long long v, float& lo, float& hi) {
    unsigned a, b;
    asm("mov.b64 {%0, %1}, %2;" : "=r"(a), "=r"(b) : "l"(v));
    lo = __uint_as_float(a);
    hi = __uint_as_float(b);
}

__device__ __forceinline__ float lrelu(float x) { return x > 0.f ? x : 0.2f * x; }

// ---------------- mma helpers ----------------
__device__ __forceinline__ uint32_t smem_u32(const void* p) {
    uint32_t a;
    asm("{ .reg .u64 t; cvta.to.shared.u64 t, %1; cvt.u32.u64 %0, t; }"
        : "=r"(a) : "l"(p));
    return a;
}
__device__ __forceinline__ void ldsm4t(uint32_t& r0, uint32_t& r1,
                                       uint32_t& r2, uint32_t& r3, uint32_t a) {
    asm volatile("ldmatrix.sync.aligned.m8n8.x4.trans.shared.b16 {%0,%1,%2,%3}, [%4];"
                 : "=r"(r0), "=r"(r1), "=r"(r2), "=r"(r3) : "r"(a));
}
__device__ __forceinline__ void mma16816(float* c, const uint32_t* a,
                                         uint32_t b0, uint32_t b1) {
    asm volatile(
        "mma.sync.aligned.m16n8k16.row.col.f32.bf16.bf16.f32 "
        "{%0,%1,%2,%3}, {%4,%5,%6,%7}, {%8,%9}, {%0,%1,%2,%3};"
        : "+f"(c[0]), "+f"(c[1]), "+f"(c[2]), "+f"(c[3])
        : "r"(a[0]), "r"(a[1]), "r"(a[2]), "r"(a[3]), "r"(b0), "r"(b1));
}

// ---------------- CSR build ----------------
__global__ void hist_kernel(const int* __restrict__ ei) {
    int e = blockIdx.x * blockDim.x + threadIdx.x;
    if (e >= TOTE) return;
    int d = (e < NE) ? ei[NE + e] : (e - NE);
    atomicAdd(&g_count[d], 1);
}

__global__ void scan_part_kernel() {
    __shared__ int sh[256];
    int t = threadIdx.x;
    int i = blockIdx.x * 256 + t;
    int c = (i < NN) ? g_count[i] : 0;
    sh[t] = c;
    __syncthreads();
    #pragma unroll
    for (int off = 128; off; off >>= 1) {
        if (t < off) sh[t] += sh[t + off];
        __syncthreads();
    }
    if (t == 0) g_part[blockIdx.x] = sh[0];
}

__global__ void scan_top_kernel() {
    __shared__ int sh[512];
    int t = threadIdx.x;
    int v = (t < SCAN_NB) ? g_part[t] : 0;
    sh[t] = v;
    __syncthreads();
    for (int off = 1; off < 512; off <<= 1) {
        int u = (t >= off) ? sh[t - off] : 0;
        __syncthreads();
        sh[t] += u;
        __syncthreads();
    }
    if (t < SCAN_NB) g_partx[t] = sh[t] - v;
}

__global__ void scan_fix_kernel() {
    __shared__ int sh[256];
    int t = threadIdx.x;
    int i = blockIdx.x * 256 + t;
    int c = (i < NN) ? g_count[i] : 0;
    sh[t] = c;
    __syncthreads();
    for (int off = 1; off < 256; off <<= 1) {
        int u = (t >= off) ? sh[t - off] : 0;
        __syncthreads();
        sh[t] += u;
        __syncthreads();
    }
    int base = g_partx[blockIdx.x];
    int ex = base + sh[t] - c;
    if (i < NN) {
        g_offs[i] = ex;
        g_cursor[i] = ex;
    }
    if (i == NN - 1) g_offs[NN] = base + sh[t];
}

__global__ void scatter_kernel(const int* __restrict__ ei) {
    int e = blockIdx.x * blockDim.x + threadIdx.x;
    if (e >= TOTE) return;
    int d, s;
    if (e < NE) {
        s = ei[e];
        d = ei[NE + e];
    } else {
        s = e - NE;
        d = e - NE;
    }
    int pos = atomicAdd(&g_cursor[d], 1);
    g_srcs[pos] = s;
}

// ---------- facc = x0 = concat; x0 hi/lo split; zero g_count ----------
__global__ void build_x0_kernel(const float* __restrict__ a,
                                const float* __restrict__ b,
                                const float* __restrict__ c) {
    int i = blockIdx.x * blockDim.x + threadIdx.x;  // over NN*16 float4
    if (i >= NN * 16) return;
    if (i < NN) g_count[i] = 0;
    int v = i >> 4;
    float4 val;
    if (v < NI)            val = ((const float4*)a)[i];
    else if (v < NI + NU)  val = ((const float4*)b)[i - NI * 16];
    else                   val = ((const float4*)c)[i - (NI + NU) * 16];
    ((float4*)g_facc)[i] = val;
    __nv_bfloat16 hx = __float2bfloat16(val.x);
    __nv_bfloat16 hy = __float2bfloat16(val.y);
    __nv_bfloat16 hz = __float2bfloat16(val.z);
    __nv_bfloat16 hw = __float2bfloat16(val.w);
    ((__nv_bfloat162*)g_x0h)[i * 2]     = __halves2bfloat162(hx, hy);
    ((__nv_bfloat162*)g_x0h)[i * 2 + 1] = __halves2bfloat162(hz, hw);
    ((__nv_bfloat162*)g_x0l)[i * 2] = __floats2bfloat162_rn(
        val.x - __bfloat162float(hx), val.y - __bfloat162float(hy));
    ((__nv_bfloat162*)g_x0l)[i * 2 + 1] = __floats2bfloat162_rn(
        val.z - __bfloat162float(hz), val.w - __bfloat162float(hw));
}

// ---------------- weight hi/lo split (elementwise, no transpose) ----------
__global__ void wsplit_kernel(const float* __restrict__ W,
                              __nv_bfloat16* __restrict__ oh,
                              __nv_bfloat16* __restrict__ ol, int n) {
    int i = blockIdx.x * blockDim.x + threadIdx.x;
    if (i >= n) return;
    float v = W[i];
    __nv_bfloat16 h = __float2bfloat16(v);
    oh[i] = h;
    ol[i] = __float2bfloat16(v - __bfloat162float(h));
}

// ---------------- HMMA GEMM + fused attention dots ----------------
// C[M,NC] = A[M,K] @ B[K,NC] via bf16 split-3 (AhBh + AhBl + AlBh), f32 accum.
// CTA: 128 rows, 8 warps x 16 rows. B (hi+lo) staged in smem; A frags from gmem.
template <int K, int NC, int AS>
__global__ void __launch_bounds__(256, 2)
mma_gemm_att(const __nv_bfloat16* __restrict__ Ah,
             const __nv_bfloat16* __restrict__ Al,
             const __nv_bfloat16* __restrict__ Bh,
             const __nv_bfloat16* __restrict__ Bl,
             float* __restrict__ C, int M,
             const float* __restrict__ vs, const float* __restrict__ vd) {
    constexpr int NCP = NC + 8;
    constexpr int NT = NC / 8;   // n-tiles
    extern __shared__ __align__(16) char smraw[];
    __nv_bfloat16* bhS = (__nv_bfloat16*)smraw;
    __nv_bfloat16* blS = bhS + K * NCP;
    __shared__ float s_vs[NC], s_vd[NC];

    const int tid = threadIdx.x, wid = tid >> 5, lane = tid & 31;

    // cooperative B load (uint4 = 8 bf16)
    for (int i = tid; i < K * NC / 8; i += 256) {
        int k = i / (NC / 8), n = (i % (NC / 8)) * 8;
        *(uint4*)&bhS[k * NCP + n] = *(const uint4*)&Bh[k * NC + n];
        *(uint4*)&blS[k * NCP + n] = *(const uint4*)&Bl[k * NC + n];
    }
    if (tid < NC) {
        s_vs[tid] = vs[tid];
        s_vd[tid] = vd[tid];
    }
    __syncthreads();

    const int r0 = blockIdx.x * 128 + wid * 16 + (lane >> 2);
    const bool v0 = (r0 < M), v1 = (r0 + 8 < M);
    const int kc = 2 * (lane & 3);

    float c[NT][4];
    #pragma unroll
    for (int j = 0; j < NT; j++)
        #pragma unroll
        for (int q = 0; q < 4; q++) c[j][q] = 0.f;

    const uint32_t bhBase = smem_u32(bhS);
    const uint32_t blBase = smem_u32(blS);
    const int krow = (lane & 7) + ((lane >> 3) & 1) * 8;
    const int ncol = (lane >> 4) * 8;

    const __nv_bfloat16* pah = Ah + (long)r0 * K + kc;
    const __nv_bfloat16* pal = Al + (long)r0 * K + kc;

    #pragma unroll
    for (int k0 = 0; k0 < K; k0 += 16) {
        uint32_t ah[4] = {0, 0, 0, 0}, al[4] = {0, 0, 0, 0};
        if (v0) {
            ah[0] = *(const uint32_t*)(pah + k0);
            ah[2] = *(const uint32_t*)(pah + k0 + 8);
            al[0] = *(const uint32_t*)(pal + k0);
            al[2] = *(const uint32_t*)(pal + k0 + 8);
        }
        if (v1) {
            ah[1] = *(const uint32_t*)(pah + 8 * K + k0);
            ah[3] = *(const uint32_t*)(pah + 8 * K + k0 + 8);
            al[1] = *(const uint32_t*)(pal + 8 * K + k0);
            al[3] = *(const uint32_t*)(pal + 8 * K + k0 + 8);
        }
        #pragma unroll
        for (int jp = 0; jp < NT / 2; jp++) {
            uint32_t off = (uint32_t)(((k0 + krow) * NCP + jp * 16 + ncol) * 2);
            uint32_t bh0, bh1, bh2, bh3, bl0, bl1, bl2, bl3;
            ldsm4t(bh0, bh1, bh2, bh3, bhBase + off);
            ldsm4t(bl0, bl1, bl2, bl3, blBase + off);
            mma16816(c[2 * jp],     ah, bh0, bh1);
            mma16816(c[2 * jp + 1], ah, bh2, bh3);
            mma16816(c[2 * jp],     ah, bl0, bl1);
            mma16816(c[2 * jp + 1], ah, bl2, bl3);
            mma16816(c[2 * jp],     al, bh0, bh1);
            mma16816(c[2 * jp + 1], al, bh2, bh3);
        }
    }

    // C store: lane owns rows r0 (c[j][0..1]) and r0+8 (c[j][2..3]) at cols 8j+kc
    if (v0) {
        #pragma unroll
        for (int j = 0; j < NT; j++)
            *(float2*)&C[(long)r0 * NC + 8 * j + kc] = make_float2(c[j][0], c[j][1]);
    }
    if (v1) {
        #pragma unroll
        for (int j = 0; j < NT; j++)
            *(float2*)&C[(long)(r0 + 8) * NC + 8 * j + kc] =
                make_float2(c[j][2], c[j][3]);
    }

    // fused attention dots per head (head h = tiles 8h..8h+7)
    #pragma unroll
    for (int h = 0; h < AS; h++) {
        float s0 = 0.f, d0 = 0.f, s1 = 0.f, d1 = 0.f;
        #pragma unroll
        for (int j = h * 8; j < h * 8 + 8; j++) {
            int col = 8 * j + kc;
            float w0 = s_vs[col], w1 = s_vs[col + 1];
            float u0 = s_vd[col], u1 = s_vd[col + 1];
            s0 += c[j][0] * w0 + c[j][1] * w1;
            d0 += c[j][0] * u0 + c[j][1] * u1;
            s1 += c[j][2] * w0 + c[j][3] * w1;
            d1 += c[j][2] * u0 + c[j][3] * u1;
        }
        #pragma unroll
        for (int o = 1; o <= 2; o <<= 1) {
            s0 += __shfl_xor_sync(0xffffffffu, s0, o);
            d0 += __shfl_xor_sync(0xffffffffu, d0, o);
            s1 += __shfl_xor_sync(0xffffffffu, s1, o);
            d1 += __shfl_xor_sync(0xffffffffu, d1, o);
        }
        if ((lane & 3) == 0) {
            if (v0) {
                g_asrc[(long)r0 * AS + h] = s0;
                g_adst[(long)r0 * AS + h] = d0;
            }
            if (v1) {
                g_asrc[(long)(r0 + 8) * AS + h] = s1;
                g_adst[(long)(r0 + 8) * AS + h] = d1;
            }
        }
    }
}

// ---------------- aggregation, H=2: one warp per (node, head) ----------------
__global__ void agg_h2_kernel(const float* __restrict__ xw,
                              const float* __restrict__ bias) {
    int gw = (blockIdx.x * blockDim.x + threadIdx.x) >> 5;
    if (gw >= 2 * NN) return;
    int v = gw >> 1, h = gw & 1;
    int lane = threadIdx.x & 31;
    int beg = g_offs[v];
    int deg = g_offs[v + 1] - beg;
    float ad = g_adst[2 * v + h];

    unsigned long long acc = 0ull;
    const unsigned long long* xh = (const unsigned long long*)xw;
    const long hoff = h * 32 + lane;

    if (deg <= 32) {
        int sidx = 0;
        float e = -3.0e38f;
        if (lane < deg) {
            sidx = g_srcs[beg + lane];
            e = lrelu(g_asrc[2 * sidx + h] + ad);
        }
        float m = e;
        #pragma unroll
        for (int o = 16; o; o >>= 1)
            m = fmaxf(m, __shfl_xor_sync(0xffffffffu, m, o));
        float p = (lane < deg) ? __expf(e - m) : 0.f;
        float ssum = p;
        #pragma unroll
        for (int o = 16; o; o >>= 1)
            ssum += __shfl_xor_sync(0xffffffffu, ssum, o);
        float inv = 1.f / (ssum + 1e-16f);
        if (lane == 0)
            g_dstat[2 * v + h] = make_float4(ad, m, inv, 0.f);
        float al = p * inv;

        int t = 0;
        for (; t + 8 <= deg; t += 8) {
            int s0 = __shfl_sync(0xffffffffu, sidx, t);
            int s1 = __shfl_sync(0xffffffffu, sidx, t + 1);
            int s2 = __shfl_sync(0xffffffffu, sidx, t + 2);
            int s3 = __shfl_sync(0xffffffffu, sidx, t + 3);
            int s4 = __shfl_sync(0xffffffffu, sidx, t + 4);
            int s5 = __shfl_sync(0xffffffffu, sidx, t + 5);
            int s6 = __shfl_sync(0xffffffffu, sidx, t + 6);
            int s7 = __shfl_sync(0xffffffffu, sidx, t + 7);
            float a0 = __shfl_sync(0xffffffffu, al, t);
            float a1 = __shfl_sync(0xffffffffu, al, t + 1);
            float a2 = __shfl_sync(0xffffffffu, al, t + 2);
            float a3 = __shfl_sync(0xffffffffu, al, t + 3);
            float a4 = __shfl_sync(0xffffffffu, al, t + 4);
            float a5 = __shfl_sync(0xffffffffu, al, t + 5);
            float a6 = __shfl_sync(0xffffffffu, al, t + 6);
            float a7 = __shfl_sync(0xffffffffu, al, t + 7);
            unsigned long long x0 = xh[(long)s0 * 64 + hoff];
            unsigned long long x1 = xh[(long)s1 * 64 + hoff];
            unsigned long long x2 = xh[(long)s2 * 64 + hoff];
            unsigned long long x3 = xh[(long)s3 * 64 + hoff];
            unsigned long long x4 = xh[(long)s4 * 64 + hoff];
            unsigned long long x5 = xh[(long)s5 * 64 + hoff];
            unsigned long long x6 = xh[(long)s6 * 64 + hoff];
            unsigned long long x7 = xh[(long)s7 * 64 + hoff];
            fma2(acc, pk2(a0, a0), x0);
            fma2(acc, pk2(a1, a1), x1);
            fma2(acc, pk2(a2, a2), x2);
            fma2(acc, pk2(a3, a3), x3);
            fma2(acc, pk2(a4, a4), x4);
            fma2(acc, pk2(a5, a5), x5);
            fma2(acc, pk2(a6, a6), x6);
            fma2(acc, pk2(a7, a7), x7);
        }
        for (; t < deg; t++) {
            int s0 = __shfl_sync(0xffffffffu, sidx, t);
            float a0 = __shfl_sync(0xffffffffu, al, t);
            unsigned long long x0 = xh[(long)s0 * 64 + hoff];
            fma2(acc, pk2(a0, a0), x0);
        }
    } else {
        float m = -3.0e38f, ssum = 0.f;
        for (int i = lane; i < deg; i += 32) {
            int sc = g_srcs[beg + i];
            float e = lrelu(g_asrc[2 * sc + h] + ad);
            float n = fmaxf(m, e);
            ssum = ssum * __expf(m - n) + __expf(e - n);
            m = n;
        }
        #pragma unroll
        for (int o = 16; o; o >>= 1) {
            float om = __shfl_xor_sync(0xffffffffu, m, o);
            float os = __shfl_xor_sync(0xffffffffu, ssum, o);
            float nm = fmaxf(m, om);
            ssum = ssum * __expf(m - nm) + os * __expf(om - nm);
            m = nm;
        }
        float inv = 1.f / (ssum + 1e-16f);
        if (lane == 0)
            g_dstat[2 * v + h] = make_float4(ad, m, inv, 0.f);

        for (int base = 0; base < deg; base += 32) {
            int i = base + lane;
            float al = 0.f;
            int sidx = 0;
            if (i < deg) {
                sidx = g_srcs[beg + i];
                al = __expf(lrelu(g_asrc[2 * sidx + h] + ad) - m) * inv;
            }
            int cnt = min(32, deg - base);
            for (int t = 0; t < cnt; t++) {
                int s0 = __shfl_sync(0xffffffffu, sidx, t);
                float a0 = __shfl_sync(0xffffffffu, al, t);
                unsigned long long x0 = xh[(long)s0 * 64 + hoff];
                fma2(acc, pk2(a0, a0), x0);
            }
        }
    }

    // epilogue: write bf16 hi/lo of relu(x) for the next GEMM; facc += 0.5*x
    float xa, xb;
    unpk2(acc, xa, xb);
    int f = h * 64 + lane * 2;
    xa += bias[f];
    xb += bias[f + 1];
    float ra = fmaxf(xa, 0.f), rb = fmaxf(xb, 0.f);
    __nv_bfloat16 ha = __float2bfloat16(ra);
    __nv_bfloat16 hb = __float2bfloat16(rb);
    long boff = (long)v * 64 + h * 32 + lane;
    ((__nv_bfloat162*)g_hh)[boff] = __halves2bfloat162(ha, hb);
    ((__nv_bfloat162*)g_hl)[boff] = __floats2bfloat162_rn(
        ra - __bfloat162float(ha), rb - __bfloat162float(hb));
    atomicAdd(&g_facc[(long)v * 64 + lane * 2], 0.5f * xa);
    atomicAdd(&g_facc[(long)v * 64 + lane * 2 + 1], 0.5f * xb);
}

// ---------------- aggregation, H=1 (layer 3) + final outputs ----------------
__global__ void agg_h1_kernel(const float* __restrict__ xw,
                              const float* __restrict__ bias,
                              float* __restrict__ out) {
    int v = (blockIdx.x * blockDim.x + threadIdx.x) >> 5;
    if (v >= NN) return;
    int lane = threadIdx.x & 31;
    int beg = g_offs[v];
    int deg = g_offs[v + 1] - beg;
    float ad = g_adst[v];

    unsigned long long acc = 0ull;
    const unsigned long long* xw1 = (const unsigned long long*)xw;

    if (deg <= 32) {
        int sidx = 0;
        float e = -3.0e38f;
        if (lane < deg) {
            sidx = g_srcs[beg + lane];
            e = lrelu(g_asrc[sidx] + ad);
        }
        float m = e;
        #pragma unroll
        for (int o = 16; o; o >>= 1)
            m = fmaxf(m, __shfl_xor_sync(0xffffffffu, m, o));
        float p = (lane < deg) ? __expf(e - m) : 0.f;
        float ssum = p;
        #pragma unroll
        for (int o = 16; o; o >>= 1)
            ssum += __shfl_xor_sync(0xffffffffu, ssum, o);
        float inv = 1.f / (ssum + 1e-16f);
        if (lane == 0)
            g_dstat[v] = make_float4(ad, m, inv, 0.f);
        float al = p * inv;

        int t = 0;
        for (; t + 8 <= deg; t += 8) {
            int s0 = __shfl_sync(0xffffffffu, sidx, t);
            int s1 = __shfl_sync(0xffffffffu, sidx, t + 1);
            int s2 = __shfl_sync(0xffffffffu, sidx, t + 2);
            int s3 = __shfl_sync(0xffffffffu, sidx, t + 3);
            int s4 = __shfl_sync(0xffffffffu, sidx, t + 4);
            int s5 = __shfl_sync(0xffffffffu, sidx, t + 5);
            int s6 = __shfl_sync(0xffffffffu, sidx, t + 6);
            int s7 = __shfl_sync(0xffffffffu, sidx, t + 7);
            float a0 = __shfl_sync(0xffffffffu, al, t);
            float a1 = __shfl_sync(0xffffffffu, al, t + 1);
            float a2 = __shfl_sync(0xffffffffu, al, t + 2);
            float a3 = __shfl_sync(0xffffffffu, al, t + 3);
            float a4 = __shfl_sync(0xffffffffu, al, t + 4);
            float a5 = __shfl_sync(0xffffffffu, al, t + 5);
            float a6 = __shfl_sync(0xffffffffu, al, t + 6);
            float a7 = __shfl_sync(0xffffffffu, al, t + 7);
            unsigned long long x0 = xw1[(long)s0 * 32 + lane];
            unsigned long long x1 = xw1[(long)s1 * 32 + lane];
            unsigned long long x2 = xw1[(long)s2 * 32 + lane];
            unsigned long long x3 = xw1[(long)s3 * 32 + lane];
            unsigned long long x4 = xw1[(long)s4 * 32 + lane];
            unsigned long long x5 = xw1[(long)s5 * 32 + lane];
            unsigned long long x6 = xw1[(long)s6 * 32 + lane];
            unsigned long long x7 = xw1[(long)s7 * 32 + lane];
            fma2(acc, pk2(a0, a0), x0);
            fma2(acc, pk2(a1, a1), x1);
            fma2(acc, pk2(a2, a2), x2);
            fma2(acc, pk2(a3, a3), x3);
            fma2(acc, pk2(a4, a4), x4);
            fma2(acc, pk2(a5, a5), x5);
            fma2(acc, pk2(a6, a6), x6);
            fma2(acc, pk2(a7, a7), x7);
        }
        for (; t < deg; t++) {
            int s0 = __shfl_sync(0xffffffffu, sidx, t);
            float a0 = __shfl_sync(0xffffffffu, al, t);
            unsigned long long x0 = xw1[(long)s0 * 32 + lane];
            fma2(acc, pk2(a0, a0), x0);
        }
    } else {
        float m = -3.0e38f, ssum = 0.f;
        for (int i = lane; i < deg; i += 32) {
            int sc = g_srcs[beg + i];
            float e = lrelu(g_asrc[sc] + ad);
            float n = fmaxf(m, e);
            ssum = ssum * __expf(m - n) + __expf(e - n);
            m = n;
        }
        #pragma unroll
        for (int o = 16; o; o >>= 1) {
            float om = __shfl_xor_sync(0xffffffffu, m, o);
            float os = __shfl_xor_sync(0xffffffffu, ssum, o);
            float nm = fmaxf(m, om);
            ssum = ssum * __expf(m - nm) + os * __expf(om - nm);
            m = nm;
        }
        float inv = 1.f / (ssum + 1e-16f);
        if (lane == 0)
            g_dstat[v] = make_float4(ad, m, inv, 0.f);

        for (int base = 0; base < deg; base += 32) {
            int i = base + lane;
            float al = 0.f;
            int sidx = 0;
            if (i < deg) {
                sidx = g_srcs[beg + i];
                al = __expf(lrelu(g_asrc[sidx] + ad) - m) * inv;
            }
            int cnt = min(32, deg - base);
            for (int t = 0; t < cnt; t++) {
                int s0 = __shfl_sync(0xffffffffu, sidx, t);
                float a0 = __shfl_sync(0xffffffffu, al, t);
                unsigned long long x0 = xw1[(long)s0 * 32 + lane];
                fma2(acc, pk2(a0, a0), x0);
            }
        }
    }

    float xa, xb;
    unpk2(acc, xa, xb);
    int f = lane * 2;
    xa += bias[f];
    xb += bias[f + 1];
    float fa = (g_facc[(long)v * 64 + f] + xa) * 0.25f;
    float fb = (g_facc[(long)v * 64 + f + 1] + xb) * 0.25f;
    out[FINALO + (long)v * 64 + f] = fa;
    out[FINALO + (long)v * 64 + f + 1] = fb;
    long seg;
    if (v < NI)            seg = ITEMO + (long)v * 64;
    else if (v < NI + NU)  seg = USERO + (long)(v - NI) * 64;
    else                   seg = FETO + (long)(v - NI - NU) * 64;
    out[seg + f] = fa;
    out[seg + f + 1] = fb;
}

// ---------------- edge-order alpha kernels (coalesced writes) ----------------
__global__ void alpha2_kernel(const int* __restrict__ ei,
                              float* __restrict__ aout) {
    int e = blockIdx.x * blockDim.x + threadIdx.x;
    if (e >= TOTE) return;
    int s, d;
    if (e < NE) {
        s = ei[e];
        d = ei[NE + e];
    } else {
        s = e - NE;
        d = e - NE;
    }
    float2 as = ((const float2*)g_asrc)[s];
    float4 d0 = g_dstat[2 * d];
    float4 d1 = g_dstat[2 * d + 1];
    float a0 = __expf(lrelu(as.x + d0.x) - d0.y) * d0.z;
    float a1 = __expf(lrelu(as.y + d1.x) - d1.y) * d1.z;
    ((float2*)aout)[e] = make_float2(a0, a1);
}

__global__ void alpha1_kernel(const int* __restrict__ ei,
                              float* __restrict__ aout) {
    int e = blockIdx.x * blockDim.x + threadIdx.x;
    if (e >= TOTE) return;
    int s, d;
    if (e < NE) {
        s = ei[e];
        d = ei[NE + e];
    } else {
        s = e - NE;
        d = e - NE;
    }
    float as = g_asrc[s];
    float4 d0 = g_dstat[d];
    aout[e] = __expf(lrelu(as + d0.x) - d0.y) * d0.z;
}

// ---------------- host launch ----------------
extern "C" void kernel_launch(void* const* d_in, const int* in_sizes, int n_in,
                              void* d_out, int out_size) {
    const int*   ei       = (const int*)d_in[0];
    const float* emb_item = (const float*)d_in[1];
    const float* emb_user = (const float*)d_in[2];
    const float* emb_fet  = (const float*)d_in[3];
    const float* W1  = (const float*)d_in[4];
    const float* as1 = (const float*)d_in[5];
    const float* ad1 = (const float*)d_in[6];
    const float* b1  = (const float*)d_in[7];
    const float* W2  = (const float*)d_in[8];
    const float* as2 = (const float*)d_in[9];
    const float* ad2 = (const float*)d_in[10];
    const float* b2  = (const float*)d_in[11];
    const float* W3  = (const float*)d_in[12];
    const float* as3 = (const float*)d_in[13];
    const float* ad3 = (const float*)d_in[14];
    const float* b3  = (const float*)d_in[15];
    float* out = (float*)d_out;

    float* xwp;
    cudaGetSymbolAddress((void**)&xwp, g_xw);
    __nv_bfloat16 *x0h, *x0l, *hh, *hl, *w1h, *w1l, *w2h, *w2l, *w3h, *w3l;
    cudaGetSymbolAddress((void**)&x0h, g_x0h);
    cudaGetSymbolAddress((void**)&x0l, g_x0l);
    cudaGetSymbolAddress((void**)&hh, g_hh);
    cudaGetSymbolAddress((void**)&hl, g_hl);
    cudaGetSymbolAddress((void**)&w1h, g_w1h);
    cudaGetSymbolAddress((void**)&w1l, g_w1l);
    cudaGetSymbolAddress((void**)&w2h, g_w2h);
    cudaGetSymbolAddress((void**)&w2l, g_w2l);
    cudaGetSymbolAddress((void**)&w3h, g_w3h);
    cudaGetSymbolAddress((void**)&w3l, g_w3l);

    const int T = 256;
    int edgeBlocks = (TOTE + T - 1) / T;
    int warpBlocks = (NN * 32 + T - 1) / T;       // one warp per node
    int warp2Blocks = (2 * NN * 32 + T - 1) / T;  // one warp per (node, head)
    int gemmBlocks = (NN + 127) / 128;            // 782

    const int SM1 = 2 * 64 * (128 + 8) * 2;    // 34816
    const int SM2 = 2 * 128 * (128 + 8) * 2;   // 69632
    const int SM3 = 2 * 128 * (64 + 8) * 2;    // 36864
    cudaFuncSetAttribute(mma_gemm_att<64, 128, 2>,
                         cudaFuncAttributeMaxDynamicSharedMemorySize, SM1);
    cudaFuncSetAttribute(mma_gemm_att<128, 128, 2>,
                         cudaFuncAttributeMaxDynamicSharedMemorySize, SM2);
    cudaFuncSetAttribute(mma_gemm_att<128, 64, 1>,
                         cudaFuncAttributeMaxDynamicSharedMemorySize, SM3);

    // idx 0: x0 concat + facc init + x0 split + count zero
    build_x0_kernel<<<(NN * 16 + T - 1) / T, T>>>(emb_item, emb_user, emb_fet);
    // idx 1: W1 split
    wsplit_kernel<<<(64 * 128 + 255) / 256, 256>>>(W1, w1h, w1l, 64 * 128);
    // idx 2: hist
    hist_kernel<<<edgeBlocks, T>>>(ei);
    // idx 3: layer-1 GEMM (profiled by ncu)
    mma_gemm_att<64, 128, 2><<<gemmBlocks, T, SM1>>>(x0h, x0l, w1h, w1l,
                                                     xwp, NN, as1, ad1);
    // finish CSR
    scan_part_kernel<<<SCAN_NB, 256>>>();
    scan_top_kernel<<<1, 512>>>();
    scan_fix_kernel<<<SCAN_NB, 256>>>();
    scatter_kernel<<<edgeBlocks, T>>>(ei);

    // layer 1 aggregation
    agg_h2_kernel<<<warp2Blocks, T>>>(xwp, b1);
    alpha2_kernel<<<edgeBlocks, T>>>(ei, out + A1OFF);

    // layer 2
    wsplit_kernel<<<(128 * 128 + 255) / 256, 256>>>(W2, w2h, w2l, 128 * 128);
    mma_gemm_att<128, 128, 2><<<gemmBlocks, T, SM2>>>(hh, hl, w2h, w2l,
                                                      xwp, NN, as2, ad2);
    agg_h2_kernel<<<warp2Blocks, T>>>(xwp, b2);
    alpha2_kernel<<<edgeBlocks, T>>>(ei, out + A2OFF);

    // layer 3
    wsplit_kernel<<<(128 * 64 + 255) / 256, 256>>>(W3, w3h, w3l, 128 * 64);
    mma_gemm_att<128, 64, 1><<<gemmBlocks, T, SM3>>>(hh, hl, w3h, w3l,
                                                     xwp, NN, as3, ad3);
    agg_h1_kernel<<<warpBlocks, T>>>(xwp, b3, out);
    alpha1_kernel<<<edgeBlocks, T>>>(ei, out + A3OFF);
}